// round 4
// baseline (speedup 1.0000x reference)
#include <cuda_runtime.h>
#include <cuda_bf16.h>

// ---------------------------------------------------------------------------
// GCNEncoder: 2-layer GCN, N=100000 nodes, d=256, E=3.2M edges (+self loops),
// output = mean over nodes -> [1,256] f32.
//
// Pipeline (all graph-capturable, no allocations; scratch in __device__ bss):
//   1. count in-degree of dst (int atomics)
//   2. dis[i] = rsqrt(deg+1)
//   3. exclusive prefix sum -> rowptr (3-kernel scan)
//   4. scatter edges into CSR by dst (atomic cursors)
//   5. h = x @ W1          (SIMT sgemm 128x128x16)
//   6. agg1: out[i] = relu( dis[i]*(sum_j h[j]*dis[j] + h[i]*dis[i]) + b1 )
//   7. h = agg1 @ W2
//   8. agg2 (no relu)
//   9. deterministic 2-stage column mean -> d_out[256]
// ---------------------------------------------------------------------------

#define NMAX 100000
#define EMAX 3200000
#define DIM  256

__device__ int   g_deg[NMAX];
__device__ float g_dis[NMAX];
__device__ int   g_rowptr[NMAX + 1];
__device__ int   g_cursor[NMAX];
__device__ int   g_col[EMAX];
__device__ float g_h[(size_t)NMAX * DIM];     // GEMM output buffer
__device__ float g_agg[(size_t)NMAX * DIM];   // aggregation output buffer
__device__ int   g_bsum[256];
__device__ float g_partial[256 * DIM];

// ---------------------------- degree / CSR build ---------------------------

__global__ void k_zero_deg(int n) {
    int i = blockIdx.x * blockDim.x + threadIdx.x;
    if (i < n) g_deg[i] = 0;
}

__global__ void k_count(const int* __restrict__ dst, int e) {
    int i = blockIdx.x * blockDim.x + threadIdx.x;
    if (i < e) atomicAdd(&g_deg[dst[i]], 1);
}

__global__ void k_dis(int n) {
    int i = blockIdx.x * blockDim.x + threadIdx.x;
    if (i < n) g_dis[i] = rsqrtf((float)g_deg[i] + 1.0f);
}

// block sums over chunks of 1024 degree entries
__global__ void k_block_sums(int n) {
    __shared__ int sh[256];
    int base = blockIdx.x * 1024;
    int s = 0;
#pragma unroll
    for (int q = 0; q < 4; q++) {
        int i = base + q * 256 + threadIdx.x;
        if (i < n) s += g_deg[i];
    }
    sh[threadIdx.x] = s;
    __syncthreads();
    for (int off = 128; off > 0; off >>= 1) {
        if (threadIdx.x < off) sh[threadIdx.x] += sh[threadIdx.x + off];
        __syncthreads();
    }
    if (threadIdx.x == 0) g_bsum[blockIdx.x] = sh[0];
}

// serial exclusive scan of block sums (nb <= 256, trivial cost)
__global__ void k_scan_bsum(int nb) {
    if (threadIdx.x == 0) {
        int acc = 0;
        for (int b = 0; b < nb; b++) {
            int v = g_bsum[b];
            g_bsum[b] = acc;
            acc += v;
        }
    }
}

// per-block exclusive scan + block offset -> rowptr, cursor
__global__ void k_scan_blocks(int n, int e_total) {
    __shared__ int sh[1024];
    int i = blockIdx.x * 1024 + threadIdx.x;
    int v = (i < n) ? g_deg[i] : 0;
    sh[threadIdx.x] = v;
    __syncthreads();
    for (int off = 1; off < 1024; off <<= 1) {
        int t = 0;
        if ((int)threadIdx.x >= off) t = sh[threadIdx.x - off];
        __syncthreads();
        sh[threadIdx.x] += t;
        __syncthreads();
    }
    int excl = sh[threadIdx.x] - v;
    if (i < n) {
        int r = excl + g_bsum[blockIdx.x];
        g_rowptr[i] = r;
        g_cursor[i] = r;
    }
    if (i == 0) g_rowptr[n] = e_total;
}

__global__ void k_scatter(const int* __restrict__ src, const int* __restrict__ dst, int e) {
    int i = blockIdx.x * blockDim.x + threadIdx.x;
    if (i < e) {
        int d = dst[i];
        int p = atomicAdd(&g_cursor[d], 1);
        g_col[p] = src[i];
    }
}

// ------------------------------- SGEMM -------------------------------------
// C[M,256] = A[M,256] @ B[256,256], 128x128 block tile, 8x8 microtile.

__global__ __launch_bounds__(256, 2)
void k_sgemm(const float* __restrict__ A, const float* __restrict__ B,
             float* __restrict__ C, int M) {
    const int BM = 128, BK = 16;
    __shared__ float As[BK][BM + 4];
    __shared__ float Bs[BK][128];

    int tid = threadIdx.x;
    int bm = blockIdx.x * BM;
    int bn = blockIdx.y * 128;
    int tx = tid & 15, ty = tid >> 4;
    int aRow = tid >> 2, aCol = (tid & 3) << 2;   // A tile: 128 rows x 16 cols
    int bRow = tid >> 5, bCol = (tid & 31) << 2;  // B tile: 16 rows x 128 cols

    float acc[8][8];
#pragma unroll
    for (int i = 0; i < 8; i++)
#pragma unroll
        for (int j = 0; j < 8; j++) acc[i][j] = 0.0f;

    for (int k0 = 0; k0 < 256; k0 += BK) {
        // load A tile (transposed into smem), guarded on M
#pragma unroll
        for (int p = 0; p < 2; p++) {
            int row = aRow + p * 64;
            int gr = bm + row;
            float4 v = make_float4(0.f, 0.f, 0.f, 0.f);
            if (gr < M) v = *(const float4*)(A + (size_t)gr * 256 + k0 + aCol);
            As[aCol + 0][row] = v.x;
            As[aCol + 1][row] = v.y;
            As[aCol + 2][row] = v.z;
            As[aCol + 3][row] = v.w;
        }
        // load B tile
#pragma unroll
        for (int p = 0; p < 2; p++) {
            int kr = bRow + p * 8;
            float4 v = *(const float4*)(B + (size_t)(k0 + kr) * 256 + bn + bCol);
            *(float4*)&Bs[kr][bCol] = v;
        }
        __syncthreads();

#pragma unroll
        for (int kk = 0; kk < BK; kk++) {
            float a[8], b[8];
            *(float4*)&a[0] = *(const float4*)&As[kk][ty * 8];
            *(float4*)&a[4] = *(const float4*)&As[kk][ty * 8 + 4];
            *(float4*)&b[0] = *(const float4*)&Bs[kk][tx * 8];
            *(float4*)&b[4] = *(const float4*)&Bs[kk][tx * 8 + 4];
#pragma unroll
            for (int i = 0; i < 8; i++)
#pragma unroll
                for (int j = 0; j < 8; j++) acc[i][j] += a[i] * b[j];
        }
        __syncthreads();
    }

#pragma unroll
    for (int i = 0; i < 8; i++) {
        int gr = bm + ty * 8 + i;
        if (gr < M) {
            float4 v0 = make_float4(acc[i][0], acc[i][1], acc[i][2], acc[i][3]);
            float4 v1 = make_float4(acc[i][4], acc[i][5], acc[i][6], acc[i][7]);
            *(float4*)(C + (size_t)gr * 256 + bn + tx * 8) = v0;
            *(float4*)(C + (size_t)gr * 256 + bn + tx * 8 + 4) = v1;
        }
    }
}

// ----------------------------- aggregation ---------------------------------
// 4 rows per block of 256 threads; 64 threads (float4 each) cover 256 cols.

template <bool RELU>
__global__ void k_aggregate(const float* __restrict__ h, const float* __restrict__ bias,
                            float* __restrict__ out, int n) {
    int lane = threadIdx.x & 63;
    int rb = threadIdx.x >> 6;
    int i = blockIdx.x * 4 + rb;
    if (i >= n) return;

    const float4* __restrict__ h4 = (const float4*)h;
    float4* __restrict__ out4 = (float4*)out;

    int s = g_rowptr[i];
    int t = g_rowptr[i + 1];
    float di = g_dis[i];

    // self loop contribution: h[i]*dis[i]
    float4 hv = h4[(size_t)i * 64 + lane];
    float4 acc;
    acc.x = hv.x * di; acc.y = hv.y * di; acc.z = hv.z * di; acc.w = hv.w * di;

    int e = s;
    for (; e + 2 <= t; e += 2) {
        int j0 = g_col[e];
        int j1 = g_col[e + 1];
        float w0 = g_dis[j0];
        float w1 = g_dis[j1];
        float4 v0 = h4[(size_t)j0 * 64 + lane];
        float4 v1 = h4[(size_t)j1 * 64 + lane];
        acc.x += v0.x * w0 + v1.x * w1;
        acc.y += v0.y * w0 + v1.y * w1;
        acc.z += v0.z * w0 + v1.z * w1;
        acc.w += v0.w * w0 + v1.w * w1;
    }
    if (e < t) {
        int j0 = g_col[e];
        float w0 = g_dis[j0];
        float4 v0 = h4[(size_t)j0 * 64 + lane];
        acc.x += v0.x * w0;
        acc.y += v0.y * w0;
        acc.z += v0.z * w0;
        acc.w += v0.w * w0;
    }

    float4 b4 = ((const float4*)bias)[lane];
    float4 r;
    r.x = acc.x * di + b4.x;
    r.y = acc.y * di + b4.y;
    r.z = acc.z * di + b4.z;
    r.w = acc.w * di + b4.w;
    if (RELU) {
        r.x = fmaxf(r.x, 0.f);
        r.y = fmaxf(r.y, 0.f);
        r.z = fmaxf(r.z, 0.f);
        r.w = fmaxf(r.w, 0.f);
    }
    out4[(size_t)i * 64 + lane] = r;
}

// ------------------------------- mean reduce -------------------------------

__global__ void k_reduce_partial(const float* __restrict__ agg, int n) {
    int c = threadIdx.x;  // 256 columns
    int rows_per = (n + 255) / 256;
    int r0 = blockIdx.x * rows_per;
    int r1 = min(r0 + rows_per, n);
    float s = 0.0f;
    for (int r = r0; r < r1; r++) s += agg[(size_t)r * 256 + c];
    g_partial[blockIdx.x * 256 + c] = s;
}

__global__ void k_reduce_final(float* __restrict__ out, int n) {
    int c = threadIdx.x;
    float s = 0.0f;
    for (int b = 0; b < 256; b++) s += g_partial[b * 256 + c];
    out[c] = s / (float)n;
}

// -------------------------------- launch -----------------------------------

extern "C" void kernel_launch(void* const* d_in, const int* in_sizes, int n_in,
                              void* d_out, int out_size) {
    const float* x  = (const float*)d_in[0];
    const float* W1 = (const float*)d_in[1];
    const float* b1 = (const float*)d_in[2];
    const float* W2 = (const float*)d_in[3];
    const float* b2 = (const float*)d_in[4];
    const int*   ei = (const int*)d_in[5];

    int n = in_sizes[0] / DIM;
    int e = in_sizes[5] / 2;
    const int* src = ei;
    const int* dst = ei + e;
    float* out = (float*)d_out;

    // device-global scratch pointers (resolved at module load)
    float* d_h;
    float* d_agg;
    cudaGetSymbolAddress((void**)&d_h, g_h);
    cudaGetSymbolAddress((void**)&d_agg, g_agg);

    int nb1024 = (n + 1023) / 1024;

    // --- CSR build ---
    k_zero_deg<<<(n + 255) / 256, 256>>>(n);
    k_count<<<(e + 255) / 256, 256>>>(dst, e);
    k_dis<<<(n + 255) / 256, 256>>>(n);
    k_block_sums<<<nb1024, 256>>>(n);
    k_scan_bsum<<<1, 32>>>(nb1024);
    k_scan_blocks<<<nb1024, 1024>>>(n, e);
    k_scatter<<<(e + 255) / 256, 256>>>(src, dst, e);

    dim3 gemm_grid((n + 127) / 128, 2);

    // --- layer 1 ---
    k_sgemm<<<gemm_grid, 256>>>(x, W1, d_h, n);
    k_aggregate<true><<<(n + 3) / 4, 256>>>(d_h, b1, d_agg, n);

    // --- layer 2 ---
    k_sgemm<<<gemm_grid, 256>>>(d_agg, W2, d_h, n);
    k_aggregate<false><<<(n + 3) / 4, 256>>>(d_h, b2, d_agg, n);

    // --- mean over nodes ---
    k_reduce_partial<<<256, 256>>>(d_agg, n);
    k_reduce_final<<<1, 256>>>(out, n);
}

// round 5
// speedup vs baseline: 1.8248x; 1.8248x over previous
#include <cuda_runtime.h>
#include <cuda_bf16.h>

// ---------------------------------------------------------------------------
// GCNEncoder, collapsed form.
//
// out = mean_i(h2) where h2 = S(h1 W2) + b2, S = D^-1/2 (A+I) D^-1/2.
// Linearity: mean(h2) = (1/n) (1^T S h1) W2 + b2 = (1/n) (sum_j c[j] h1[j]) W2 + b2
//   c[j] = dis[j] * ( sum_{edges src=j} dis[dst] + dis[j] )
// h1[i] = relu( dis[i]*(sum_{j in N_in(i)} (x W1)[j] dis[j] + (x W1)[i] dis[i]) + b1 )
//
// Pipeline:
//   1. CSR build by dst (count / rsqrt / scan / scatter)
//   2. coef[src] += dis[dst]  (float atomics over edges);  c[j] = dis[j]*(coef[j]+dis[j])
//   3. h = x @ W1                       (SIMT sgemm 128x128x16)
//   4. fused aggregate: per node compute relu row, accumulate c[i]*row into
//      per-block 256-wide partials (h1 never written to global)
//   5. reduce partials -> z[256];  out = (z/n) @ W2 + b2
// ---------------------------------------------------------------------------

#define NMAX 100000
#define EMAX 3200000
#define DIM  256
#define AGG_BLOCKS ((NMAX + 3) / 4)

__device__ int   g_deg[NMAX];
__device__ float g_dis[NMAX];
__device__ float g_coef[NMAX];
__device__ float g_c[NMAX];
__device__ int   g_rowptr[NMAX + 1];
__device__ int   g_cursor[NMAX];
__device__ int   g_col[EMAX];
__device__ float g_h[(size_t)NMAX * DIM];          // GEMM output
__device__ float g_part[(size_t)AGG_BLOCKS * DIM]; // per-agg-block partials
__device__ float g_part2[256 * DIM];               // stage-2 partials
__device__ int   g_bsum[256];

// ---------------------------- degree / CSR build ---------------------------

__global__ void k_zero(int n) {
    int i = blockIdx.x * blockDim.x + threadIdx.x;
    if (i < n) { g_deg[i] = 0; g_coef[i] = 0.0f; }
}

__global__ void k_count(const int* __restrict__ dst, int e) {
    int i = blockIdx.x * blockDim.x + threadIdx.x;
    if (i < e) atomicAdd(&g_deg[dst[i]], 1);
}

__global__ void k_dis(int n) {
    int i = blockIdx.x * blockDim.x + threadIdx.x;
    if (i < n) g_dis[i] = rsqrtf((float)g_deg[i] + 1.0f);
}

__global__ void k_coef(const int* __restrict__ src, const int* __restrict__ dst, int e) {
    int i = blockIdx.x * blockDim.x + threadIdx.x;
    if (i < e) atomicAdd(&g_coef[src[i]], g_dis[dst[i]]);
}

__global__ void k_cfinal(int n) {
    int i = blockIdx.x * blockDim.x + threadIdx.x;
    if (i < n) {
        float d = g_dis[i];
        g_c[i] = d * (g_coef[i] + d);
    }
}

__global__ void k_block_sums(int n) {
    __shared__ int sh[256];
    int base = blockIdx.x * 1024;
    int s = 0;
#pragma unroll
    for (int q = 0; q < 4; q++) {
        int i = base + q * 256 + threadIdx.x;
        if (i < n) s += g_deg[i];
    }
    sh[threadIdx.x] = s;
    __syncthreads();
    for (int off = 128; off > 0; off >>= 1) {
        if (threadIdx.x < off) sh[threadIdx.x] += sh[threadIdx.x + off];
        __syncthreads();
    }
    if (threadIdx.x == 0) g_bsum[blockIdx.x] = sh[0];
}

__global__ void k_scan_bsum(int nb) {
    if (threadIdx.x == 0) {
        int acc = 0;
        for (int b = 0; b < nb; b++) {
            int v = g_bsum[b];
            g_bsum[b] = acc;
            acc += v;
        }
    }
}

__global__ void k_scan_blocks(int n, int e_total) {
    __shared__ int sh[1024];
    int i = blockIdx.x * 1024 + threadIdx.x;
    int v = (i < n) ? g_deg[i] : 0;
    sh[threadIdx.x] = v;
    __syncthreads();
    for (int off = 1; off < 1024; off <<= 1) {
        int t = 0;
        if ((int)threadIdx.x >= off) t = sh[threadIdx.x - off];
        __syncthreads();
        sh[threadIdx.x] += t;
        __syncthreads();
    }
    int excl = sh[threadIdx.x] - v;
    if (i < n) {
        int r = excl + g_bsum[blockIdx.x];
        g_rowptr[i] = r;
        g_cursor[i] = r;
    }
    if (i == 0) g_rowptr[n] = e_total;
}

__global__ void k_scatter(const int* __restrict__ src, const int* __restrict__ dst, int e) {
    int i = blockIdx.x * blockDim.x + threadIdx.x;
    if (i < e) {
        int d = dst[i];
        int p = atomicAdd(&g_cursor[d], 1);
        g_col[p] = src[i];
    }
}

// ------------------------------- SGEMM -------------------------------------

__global__ __launch_bounds__(256, 2)
void k_sgemm(const float* __restrict__ A, const float* __restrict__ B,
             float* __restrict__ C, int M) {
    const int BM = 128, BK = 16;
    __shared__ float As[BK][BM + 4];
    __shared__ float Bs[BK][128];

    int tid = threadIdx.x;
    int bm = blockIdx.x * BM;
    int bn = blockIdx.y * 128;
    int tx = tid & 15, ty = tid >> 4;
    int aRow = tid >> 2, aCol = (tid & 3) << 2;
    int bRow = tid >> 5, bCol = (tid & 31) << 2;

    float acc[8][8];
#pragma unroll
    for (int i = 0; i < 8; i++)
#pragma unroll
        for (int j = 0; j < 8; j++) acc[i][j] = 0.0f;

    for (int k0 = 0; k0 < 256; k0 += BK) {
#pragma unroll
        for (int p = 0; p < 2; p++) {
            int row = aRow + p * 64;
            int gr = bm + row;
            float4 v = make_float4(0.f, 0.f, 0.f, 0.f);
            if (gr < M) v = *(const float4*)(A + (size_t)gr * 256 + k0 + aCol);
            As[aCol + 0][row] = v.x;
            As[aCol + 1][row] = v.y;
            As[aCol + 2][row] = v.z;
            As[aCol + 3][row] = v.w;
        }
#pragma unroll
        for (int p = 0; p < 2; p++) {
            int kr = bRow + p * 8;
            float4 v = *(const float4*)(B + (size_t)(k0 + kr) * 256 + bn + bCol);
            *(float4*)&Bs[kr][bCol] = v;
        }
        __syncthreads();

#pragma unroll
        for (int kk = 0; kk < BK; kk++) {
            float a[8], b[8];
            *(float4*)&a[0] = *(const float4*)&As[kk][ty * 8];
            *(float4*)&a[4] = *(const float4*)&As[kk][ty * 8 + 4];
            *(float4*)&b[0] = *(const float4*)&Bs[kk][tx * 8];
            *(float4*)&b[4] = *(const float4*)&Bs[kk][tx * 8 + 4];
#pragma unroll
            for (int i = 0; i < 8; i++)
#pragma unroll
                for (int j = 0; j < 8; j++) acc[i][j] += a[i] * b[j];
        }
        __syncthreads();
    }

#pragma unroll
    for (int i = 0; i < 8; i++) {
        int gr = bm + ty * 8 + i;
        if (gr < M) {
            float4 v0 = make_float4(acc[i][0], acc[i][1], acc[i][2], acc[i][3]);
            float4 v1 = make_float4(acc[i][4], acc[i][5], acc[i][6], acc[i][7]);
            *(float4*)(C + (size_t)gr * 256 + bn + tx * 8) = v0;
            *(float4*)(C + (size_t)gr * 256 + bn + tx * 8 + 4) = v1;
        }
    }
}

// -------------------- fused aggregation + weighted reduce -------------------
// 4 rows / block, 64 lanes (float4) per row. Computes h1 row (bias+relu),
// scales by c[i], accumulates across the block's 4 rows, writes one 256-wide
// partial per block. h1 is never materialized in global memory.

__global__ __launch_bounds__(256)
void k_agg_fused(const float* __restrict__ h, const float* __restrict__ bias, int n) {
    __shared__ float sh[4][256];

    int lane = threadIdx.x & 63;
    int rb = threadIdx.x >> 6;
    int i = blockIdx.x * 4 + rb;

    const float4* __restrict__ h4 = (const float4*)h;
    float4 res = make_float4(0.f, 0.f, 0.f, 0.f);

    if (i < n) {
        int s = g_rowptr[i];
        int t = g_rowptr[i + 1];
        float di = g_dis[i];

        float4 hv = h4[(size_t)i * 64 + lane];
        float4 acc;
        acc.x = hv.x * di; acc.y = hv.y * di; acc.z = hv.z * di; acc.w = hv.w * di;

        int e = s;
        for (; e + 2 <= t; e += 2) {
            int j0 = g_col[e];
            int j1 = g_col[e + 1];
            float w0 = g_dis[j0];
            float w1 = g_dis[j1];
            float4 v0 = h4[(size_t)j0 * 64 + lane];
            float4 v1 = h4[(size_t)j1 * 64 + lane];
            acc.x += v0.x * w0 + v1.x * w1;
            acc.y += v0.y * w0 + v1.y * w1;
            acc.z += v0.z * w0 + v1.z * w1;
            acc.w += v0.w * w0 + v1.w * w1;
        }
        if (e < t) {
            int j0 = g_col[e];
            float w0 = g_dis[j0];
            float4 v0 = h4[(size_t)j0 * 64 + lane];
            acc.x += v0.x * w0;
            acc.y += v0.y * w0;
            acc.z += v0.z * w0;
            acc.w += v0.w * w0;
        }

        float4 b4 = ((const float4*)bias)[lane];
        float ci = g_c[i];
        res.x = fmaxf(acc.x * di + b4.x, 0.f) * ci;
        res.y = fmaxf(acc.y * di + b4.y, 0.f) * ci;
        res.z = fmaxf(acc.z * di + b4.z, 0.f) * ci;
        res.w = fmaxf(acc.w * di + b4.w, 0.f) * ci;
    }

    *(float4*)&sh[rb][lane * 4] = res;
    __syncthreads();

    int c = threadIdx.x;
    float s = sh[0][c] + sh[1][c] + sh[2][c] + sh[3][c];
    g_part[(size_t)blockIdx.x * 256 + c] = s;
}

// ------------------------------- reductions --------------------------------

__global__ void k_reduce_stage1(int nb) {
    int c = threadIdx.x;
    int rows_per = (nb + 255) / 256;
    int r0 = blockIdx.x * rows_per;
    int r1 = min(r0 + rows_per, nb);
    float s = 0.0f;
    for (int r = r0; r < r1; r++) s += g_part[(size_t)r * 256 + c];
    g_part2[blockIdx.x * 256 + c] = s;
}

// z[c] = sum partials / n ; out[d] = b2[d] + sum_k z[k] * W2[k,d]
__global__ void k_final(const float* __restrict__ W2, const float* __restrict__ b2,
                        float* __restrict__ out, int n) {
    __shared__ float z[256];
    int c = threadIdx.x;
    float s = 0.0f;
    for (int b = 0; b < 256; b++) s += g_part2[b * 256 + c];
    z[c] = s / (float)n;
    __syncthreads();

    float o = b2[c];
#pragma unroll 8
    for (int k = 0; k < 256; k++) o += z[k] * W2[k * 256 + c];
    out[c] = o;
}

// -------------------------------- launch -----------------------------------

extern "C" void kernel_launch(void* const* d_in, const int* in_sizes, int n_in,
                              void* d_out, int out_size) {
    const float* x  = (const float*)d_in[0];
    const float* W1 = (const float*)d_in[1];
    const float* b1 = (const float*)d_in[2];
    const float* W2 = (const float*)d_in[3];
    const float* b2 = (const float*)d_in[4];
    const int*   ei = (const int*)d_in[5];

    int n = in_sizes[0] / DIM;
    int e = in_sizes[5] / 2;
    const int* src = ei;
    const int* dst = ei + e;
    float* out = (float*)d_out;

    float* d_h;
    cudaGetSymbolAddress((void**)&d_h, g_h);

    int nb1024 = (n + 1023) / 1024;
    int agg_blocks = (n + 3) / 4;

    // --- CSR build + coefficients ---
    k_zero<<<(n + 255) / 256, 256>>>(n);
    k_count<<<(e + 255) / 256, 256>>>(dst, e);
    k_dis<<<(n + 255) / 256, 256>>>(n);
    k_coef<<<(e + 255) / 256, 256>>>(src, dst, e);
    k_cfinal<<<(n + 255) / 256, 256>>>(n);
    k_block_sums<<<nb1024, 256>>>(n);
    k_scan_bsum<<<1, 32>>>(nb1024);
    k_scan_blocks<<<nb1024, 1024>>>(n, e);
    k_scatter<<<(e + 255) / 256, 256>>>(src, dst, e);

    // --- layer 1 GEMM ---
    dim3 gemm_grid((n + 127) / 128, 2);
    k_sgemm<<<gemm_grid, 256>>>(x, W1, d_h, n);

    // --- fused aggregate + relu + weighted reduce (layer 2 collapsed) ---
    k_agg_fused<<<agg_blocks, 256>>>(d_h, b1, n);

    // --- reduce partials, matvec with W2, bias, mean ---
    k_reduce_stage1<<<256, 256>>>(agg_blocks);
    k_final<<<1, 256>>>(W2, b2, out, n);
}

// round 6
// speedup vs baseline: 2.4448x; 1.3398x over previous
#include <cuda_runtime.h>
#include <cuda_bf16.h>
#include <cstdint>

// ---------------------------------------------------------------------------
// GCNEncoder, collapsed form + tensor-core layer-1 GEMM + bf16 h' gather.
//
// out = (1/n) (sum_j c[j] h1[j]) W2 + b2
//   c[j]  = dis[j] * ( sum_{edges src=j} dis[dst] + dis[j] )
//   h1[i] = relu( dis[i]*(sum_{j in N_in(i)} h'[j] + h'[i]) + b1 )
//   h'[j] = (x W1)[j] * dis[j]    (stored bf16, so the edge gather needs no
//                                  per-edge dis lookup and is half the bytes)
//
// GEMM is split-tf32 (hi+lo, 3 mma terms) -> fp32-class accuracy on tensor
// cores. Aggregation gathers bf16 rows (L2-resident, 51 MB working set).
// ---------------------------------------------------------------------------

#define NMAX 100000
#define EMAX 3200000
#define DIM  256
#define AGG_BLOCKS ((NMAX + 7) / 8)

__device__ int   g_deg[NMAX];
__device__ float g_dis[NMAX];
__device__ float g_coef[NMAX];
__device__ float g_c[NMAX];
__device__ int   g_rowptr[NMAX + 1];
__device__ int   g_cursor[NMAX];
__device__ int   g_col[EMAX];
__device__ __align__(16) __nv_bfloat16 g_hb[(size_t)NMAX * DIM];  // h' bf16
__device__ float g_part[(size_t)AGG_BLOCKS * DIM];
__device__ float g_part2[256 * DIM];
__device__ int   g_bsum[256];

// ---------------------------- degree / CSR build ---------------------------

__global__ void k_zero(int n) {
    int i = blockIdx.x * blockDim.x + threadIdx.x;
    if (i < n) { g_deg[i] = 0; g_coef[i] = 0.0f; }
}

__global__ void k_count(const int* __restrict__ dst, int e) {
    int i = blockIdx.x * blockDim.x + threadIdx.x;
    if (i < e) atomicAdd(&g_deg[dst[i]], 1);
}

// block sums over 1024-entry chunks of deg; also computes dis = rsqrt(deg+1)
__global__ void k_block_sums(int n) {
    __shared__ int sh[256];
    int base = blockIdx.x * 1024;
    int s = 0;
#pragma unroll
    for (int q = 0; q < 4; q++) {
        int i = base + q * 256 + threadIdx.x;
        if (i < n) {
            int d = g_deg[i];
            s += d;
            g_dis[i] = rsqrtf((float)d + 1.0f);
        }
    }
    sh[threadIdx.x] = s;
    __syncthreads();
    for (int off = 128; off > 0; off >>= 1) {
        if (threadIdx.x < off) sh[threadIdx.x] += sh[threadIdx.x + off];
        __syncthreads();
    }
    if (threadIdx.x == 0) g_bsum[blockIdx.x] = sh[0];
}

__global__ void k_scan_bsum(int nb) {
    if (threadIdx.x == 0) {
        int acc = 0;
        for (int b = 0; b < nb; b++) {
            int v = g_bsum[b];
            g_bsum[b] = acc;
            acc += v;
        }
    }
}

__global__ void k_scan_blocks(int n, int e_total) {
    __shared__ int sh[1024];
    int i = blockIdx.x * 1024 + threadIdx.x;
    int v = (i < n) ? g_deg[i] : 0;
    sh[threadIdx.x] = v;
    __syncthreads();
    for (int off = 1; off < 1024; off <<= 1) {
        int t = 0;
        if ((int)threadIdx.x >= off) t = sh[threadIdx.x - off];
        __syncthreads();
        sh[threadIdx.x] += t;
        __syncthreads();
    }
    int excl = sh[threadIdx.x] - v;
    if (i < n) {
        int r = excl + g_bsum[blockIdx.x];
        g_rowptr[i] = r;
        g_cursor[i] = r;
    }
    if (i == 0) g_rowptr[n] = e_total;
}

// scatter into CSR by dst; fold the coef accumulation (sum over src) in here
__global__ void k_scatter(const int* __restrict__ src, const int* __restrict__ dst, int e) {
    int i = blockIdx.x * blockDim.x + threadIdx.x;
    if (i < e) {
        int s = src[i];
        int d = dst[i];
        int p = atomicAdd(&g_cursor[d], 1);
        g_col[p] = s;
        atomicAdd(&g_coef[s], g_dis[d]);
    }
}

__global__ void k_cfinal(int n) {
    int i = blockIdx.x * blockDim.x + threadIdx.x;
    if (i < n) {
        float d = g_dis[i];
        g_c[i] = d * (g_coef[i] + d);
    }
}

// --------------------------- split-tf32 GEMM -------------------------------
// h'[M,256] = (A[M,256] @ B[256,256]) * dis[row], stored bf16.
// BM=128, BN=128 (grid.y=2), BK=16. 8 warps, warp tile 32x64, m16n8k8 atoms.
// Split each input v = hi + lo (both tf32); D += Ahi*Bhi + Alo*Bhi + Ahi*Blo.

__device__ __forceinline__ uint32_t f2tf32(float x) {
    uint32_t u;
    asm("cvt.rna.tf32.f32 %0, %1;" : "=r"(u) : "f"(x));
    return u;
}

__device__ __forceinline__ void mma_tf32(float* d, const uint32_t* a, const uint32_t* b) {
    asm volatile(
        "mma.sync.aligned.m16n8k8.row.col.f32.tf32.tf32.f32 "
        "{%0,%1,%2,%3}, {%4,%5,%6,%7}, {%8,%9}, {%0,%1,%2,%3};\n"
        : "+f"(d[0]), "+f"(d[1]), "+f"(d[2]), "+f"(d[3])
        : "r"(a[0]), "r"(a[1]), "r"(a[2]), "r"(a[3]), "r"(b[0]), "r"(b[1]));
}

#define F2U __float_as_uint

__global__ __launch_bounds__(256, 2)
void k_gemm_tf32(const float* __restrict__ A, const float* __restrict__ B, int M) {
    __shared__ float Ah[128][20], Al[128][20];   // [m][k], stride 20 (conflict-free)
    __shared__ float Bh[16][136], Bl[16][136];   // [k][n], stride 136 (136%32==8)

    int tid = threadIdx.x;
    int bm = blockIdx.x * 128;
    int bn = blockIdx.y * 128;
    int wid = tid >> 5;
    int lane = tid & 31;
    int wm = (wid & 3) * 32;
    int wn = (wid >> 2) * 64;
    int qr = lane >> 2, qc = lane & 3;

    float d[2][8][4];
#pragma unroll
    for (int i = 0; i < 2; i++)
#pragma unroll
        for (int j = 0; j < 8; j++)
#pragma unroll
            for (int q = 0; q < 4; q++) d[i][j][q] = 0.0f;

    for (int k0 = 0; k0 < 256; k0 += 16) {
        // A tile: 128x16 floats = 512 float4, 2 per thread
#pragma unroll
        for (int p = 0; p < 2; p++) {
            int idx = tid + p * 256;
            int row = idx >> 2, c4 = (idx & 3) << 2;
            int gr = bm + row;
            float4 v = make_float4(0.f, 0.f, 0.f, 0.f);
            if (gr < M) v = *(const float4*)(A + (size_t)gr * 256 + k0 + c4);
            float hx = __uint_as_float(f2tf32(v.x));
            float hy = __uint_as_float(f2tf32(v.y));
            float hz = __uint_as_float(f2tf32(v.z));
            float hw = __uint_as_float(f2tf32(v.w));
            Ah[row][c4 + 0] = hx; Al[row][c4 + 0] = __uint_as_float(f2tf32(v.x - hx));
            Ah[row][c4 + 1] = hy; Al[row][c4 + 1] = __uint_as_float(f2tf32(v.y - hy));
            Ah[row][c4 + 2] = hz; Al[row][c4 + 2] = __uint_as_float(f2tf32(v.z - hz));
            Ah[row][c4 + 3] = hw; Al[row][c4 + 3] = __uint_as_float(f2tf32(v.w - hw));
        }
        // B tile: 16x128 floats = 512 float4, 2 per thread
#pragma unroll
        for (int p = 0; p < 2; p++) {
            int idx = tid + p * 256;
            int kr = idx >> 5, n4 = (idx & 31) << 2;
            float4 v = *(const float4*)(B + (size_t)(k0 + kr) * 256 + bn + n4);
            float hx = __uint_as_float(f2tf32(v.x));
            float hy = __uint_as_float(f2tf32(v.y));
            float hz = __uint_as_float(f2tf32(v.z));
            float hw = __uint_as_float(f2tf32(v.w));
            Bh[kr][n4 + 0] = hx; Bl[kr][n4 + 0] = __uint_as_float(f2tf32(v.x - hx));
            Bh[kr][n4 + 1] = hy; Bl[kr][n4 + 1] = __uint_as_float(f2tf32(v.y - hy));
            Bh[kr][n4 + 2] = hz; Bl[kr][n4 + 2] = __uint_as_float(f2tf32(v.z - hz));
            Bh[kr][n4 + 3] = hw; Bl[kr][n4 + 3] = __uint_as_float(f2tf32(v.w - hw));
        }
        __syncthreads();

#pragma unroll
        for (int ks = 0; ks < 2; ks++) {
            int kb = ks * 8;
            uint32_t ah[2][4], al[2][4];
#pragma unroll
            for (int ma = 0; ma < 2; ma++) {
                int r = wm + 16 * ma + qr;
                ah[ma][0] = F2U(Ah[r][kb + qc]);
                ah[ma][1] = F2U(Ah[r + 8][kb + qc]);
                ah[ma][2] = F2U(Ah[r][kb + qc + 4]);
                ah[ma][3] = F2U(Ah[r + 8][kb + qc + 4]);
                al[ma][0] = F2U(Al[r][kb + qc]);
                al[ma][1] = F2U(Al[r + 8][kb + qc]);
                al[ma][2] = F2U(Al[r][kb + qc + 4]);
                al[ma][3] = F2U(Al[r + 8][kb + qc + 4]);
            }
#pragma unroll
            for (int na = 0; na < 8; na++) {
                int nn = wn + 8 * na + qr;
                uint32_t bh[2], bl[2];
                bh[0] = F2U(Bh[kb + qc][nn]);
                bh[1] = F2U(Bh[kb + qc + 4][nn]);
                bl[0] = F2U(Bl[kb + qc][nn]);
                bl[1] = F2U(Bl[kb + qc + 4][nn]);
                mma_tf32(d[0][na], ah[0], bh);
                mma_tf32(d[1][na], ah[1], bh);
                mma_tf32(d[0][na], al[0], bh);
                mma_tf32(d[1][na], al[1], bh);
                mma_tf32(d[0][na], ah[0], bl);
                mma_tf32(d[1][na], ah[1], bl);
            }
        }
        __syncthreads();
    }

    // epilogue: multiply by dis[row], convert to bf16, store pairs
#pragma unroll
    for (int ma = 0; ma < 2; ma++) {
        int r0 = bm + wm + 16 * ma + qr;
        int r1 = r0 + 8;
        float w0 = (r0 < M) ? g_dis[r0] : 0.0f;
        float w1 = (r1 < M) ? g_dis[r1] : 0.0f;
#pragma unroll
        for (int na = 0; na < 8; na++) {
            int c = bn + wn + 8 * na + 2 * qc;
            if (r0 < M) {
                __nv_bfloat162 p = __floats2bfloat162_rn(d[ma][na][0] * w0, d[ma][na][1] * w0);
                *(__nv_bfloat162*)(&g_hb[(size_t)r0 * 256 + c]) = p;
            }
            if (r1 < M) {
                __nv_bfloat162 p = __floats2bfloat162_rn(d[ma][na][2] * w1, d[ma][na][3] * w1);
                *(__nv_bfloat162*)(&g_hb[(size_t)r1 * 256 + c]) = p;
            }
        }
    }
}

// -------------------- fused aggregation + weighted reduce -------------------
// 8 rows / block (one warp per row). Lane l owns cols l*8..l*8+7 (one uint4
// of 8 bf16). Gather is pure row adds (dis already folded into h').

__device__ __forceinline__ void add8(float* acc, uint4 v) {
    acc[0] += __uint_as_float(v.x << 16);
    acc[1] += __uint_as_float(v.x & 0xffff0000u);
    acc[2] += __uint_as_float(v.y << 16);
    acc[3] += __uint_as_float(v.y & 0xffff0000u);
    acc[4] += __uint_as_float(v.z << 16);
    acc[5] += __uint_as_float(v.z & 0xffff0000u);
    acc[6] += __uint_as_float(v.w << 16);
    acc[7] += __uint_as_float(v.w & 0xffff0000u);
}

__global__ __launch_bounds__(256)
void k_agg_fused(const float* __restrict__ bias, int n) {
    __shared__ float sh[8][256];

    int lane = threadIdx.x & 31;
    int w = threadIdx.x >> 5;
    int i = blockIdx.x * 8 + w;

    const uint4* __restrict__ hp = (const uint4*)g_hb;
    float res[8];
#pragma unroll
    for (int q = 0; q < 8; q++) res[q] = 0.0f;

    if (i < n) {
        int s = g_rowptr[i];
        int t = g_rowptr[i + 1];
        float di = g_dis[i];
        float ci = g_c[i];

        float acc[8];
        // self loop: h'[i]
        uint4 sv = hp[(size_t)i * 32 + lane];
        acc[0] = __uint_as_float(sv.x << 16);
        acc[1] = __uint_as_float(sv.x & 0xffff0000u);
        acc[2] = __uint_as_float(sv.y << 16);
        acc[3] = __uint_as_float(sv.y & 0xffff0000u);
        acc[4] = __uint_as_float(sv.z << 16);
        acc[5] = __uint_as_float(sv.z & 0xffff0000u);
        acc[6] = __uint_as_float(sv.w << 16);
        acc[7] = __uint_as_float(sv.w & 0xffff0000u);

        for (int base = s; base < t; base += 32) {
            int m = min(32, t - base);
            int jv = (base + lane < t) ? g_col[base + lane] : 0;
#pragma unroll 4
            for (int k = 0; k < m; k++) {
                int j = __shfl_sync(0xffffffffu, jv, k);
                add8(acc, hp[(size_t)j * 32 + lane]);
            }
        }

        float4 b0 = *(const float4*)(bias + lane * 8);
        float4 b1 = *(const float4*)(bias + lane * 8 + 4);
        res[0] = fmaxf(acc[0] * di + b0.x, 0.f) * ci;
        res[1] = fmaxf(acc[1] * di + b0.y, 0.f) * ci;
        res[2] = fmaxf(acc[2] * di + b0.z, 0.f) * ci;
        res[3] = fmaxf(acc[3] * di + b0.w, 0.f) * ci;
        res[4] = fmaxf(acc[4] * di + b1.x, 0.f) * ci;
        res[5] = fmaxf(acc[5] * di + b1.y, 0.f) * ci;
        res[6] = fmaxf(acc[6] * di + b1.z, 0.f) * ci;
        res[7] = fmaxf(acc[7] * di + b1.w, 0.f) * ci;
    }

#pragma unroll
    for (int q = 0; q < 8; q++) sh[w][lane * 8 + q] = res[q];
    __syncthreads();

    int c = threadIdx.x;
    float ssum = 0.0f;
#pragma unroll
    for (int q = 0; q < 8; q++) ssum += sh[q][c];
    g_part[(size_t)blockIdx.x * 256 + c] = ssum;
}

// ------------------------------- reductions --------------------------------

__global__ void k_reduce_stage1(int nb) {
    int c = threadIdx.x;
    int rows_per = (nb + 255) / 256;
    int r0 = blockIdx.x * rows_per;
    int r1 = min(r0 + rows_per, nb);
    float s = 0.0f;
    for (int r = r0; r < r1; r++) s += g_part[(size_t)r * 256 + c];
    g_part2[blockIdx.x * 256 + c] = s;
}

__global__ void k_final(const float* __restrict__ W2, const float* __restrict__ b2,
                        float* __restrict__ out, int n) {
    __shared__ float z[256];
    int c = threadIdx.x;
    float s = 0.0f;
    for (int b = 0; b < 256; b++) s += g_part2[b * 256 + c];
    z[c] = s / (float)n;
    __syncthreads();

    float o = b2[c];
#pragma unroll 8
    for (int k = 0; k < 256; k++) o += z[k] * W2[k * 256 + c];
    out[c] = o;
}

// -------------------------------- launch -----------------------------------

extern "C" void kernel_launch(void* const* d_in, const int* in_sizes, int n_in,
                              void* d_out, int out_size) {
    const float* x  = (const float*)d_in[0];
    const float* W1 = (const float*)d_in[1];
    const float* b1 = (const float*)d_in[2];
    const float* W2 = (const float*)d_in[3];
    const float* b2 = (const float*)d_in[4];
    const int*   ei = (const int*)d_in[5];

    int n = in_sizes[0] / DIM;
    int e = in_sizes[5] / 2;
    const int* src = ei;
    const int* dst = ei + e;
    float* out = (float*)d_out;

    int nb1024 = (n + 1023) / 1024;
    int agg_blocks = (n + 7) / 8;

    // --- CSR build + coefficients ---
    k_zero<<<(n + 255) / 256, 256>>>(n);
    k_count<<<(e + 255) / 256, 256>>>(dst, e);
    k_block_sums<<<nb1024, 256>>>(n);     // also computes dis
    k_scan_bsum<<<1, 32>>>(nb1024);
    k_scan_blocks<<<nb1024, 1024>>>(n, e);
    k_scatter<<<(e + 255) / 256, 256>>>(src, dst, e);  // also accumulates coef
    k_cfinal<<<(n + 255) / 256, 256>>>(n);

    // --- layer 1 GEMM (tensor cores, split-tf32), h' = (x W1) * dis bf16 ---
    dim3 gemm_grid((n + 127) / 128, 2);
    k_gemm_tf32<<<gemm_grid, 256>>>(x, W1, n);

    // --- fused aggregate + relu + weighted reduce (layer 2 collapsed) ---
    k_agg_fused<<<agg_blocks, 256>>>(b1, n);

    // --- reduce partials, matvec with W2, bias, mean ---
    k_reduce_stage1<<<256, 256>>>(agg_blocks);
    k_final<<<1, 256>>>(W2, b2, out, n);
}

// round 7
// speedup vs baseline: 3.6959x; 1.5117x over previous
#include <cuda_runtime.h>
#include <cuda_bf16.h>
#include <cstdint>

// ---------------------------------------------------------------------------
// GCNEncoder, collapsed form. Layer-1 GEMM = bf16 hi/lo split (3-term) on
// tensor cores with ldmatrix fragment loads; edge gather in bf16 (L2-resident).
//
// out = (1/n) (sum_j c[j] h1[j]) W2 + b2
//   c[j]  = dis[j] * ( sum_{edges src=j} dis[dst] + dis[j] )
//   h1[i] = relu( dis[i]*(sum_{j in N_in(i)} h'[j] + h'[i]) + b1 )
//   h'[j] = (x W1)[j] * dis[j]   (bf16)
// ---------------------------------------------------------------------------

#define NMAX 100000
#define EMAX 3200000
#define DIM  256
#define AGG_BLOCKS ((NMAX + 7) / 8)

__device__ int   g_deg[NMAX];
__device__ float g_dis[NMAX];
__device__ float g_coef[NMAX];
__device__ int   g_rowptr[NMAX + 1];
__device__ int   g_cursor[NMAX];
__device__ int   g_col[EMAX];
__device__ __align__(16) __nv_bfloat16 g_hb[(size_t)NMAX * DIM];
__device__ float g_part[(size_t)AGG_BLOCKS * DIM];
__device__ float g_part2[256 * DIM];
__device__ int   g_bsum[256];

// ---------------------------- degree / CSR build ---------------------------

__global__ void k_zero(int n) {
    int i = blockIdx.x * blockDim.x + threadIdx.x;
    if (i < n) { g_deg[i] = 0; g_coef[i] = 0.0f; }
}

__global__ void k_count(const int* __restrict__ dst, int e) {
    int i = blockIdx.x * blockDim.x + threadIdx.x;
    if (i < e) atomicAdd(&g_deg[dst[i]], 1);
}

// block sums over 1024-entry chunks; also computes dis = rsqrt(deg+1)
__global__ void k_block_sums(int n) {
    __shared__ int sh[256];
    int base = blockIdx.x * 1024;
    int s = 0;
#pragma unroll
    for (int q = 0; q < 4; q++) {
        int i = base + q * 256 + threadIdx.x;
        if (i < n) {
            int d = g_deg[i];
            s += d;
            g_dis[i] = rsqrtf((float)d + 1.0f);
        }
    }
    sh[threadIdx.x] = s;
    __syncthreads();
    for (int off = 128; off > 0; off >>= 1) {
        if (threadIdx.x < off) sh[threadIdx.x] += sh[threadIdx.x + off];
        __syncthreads();
    }
    if (threadIdx.x == 0) g_bsum[blockIdx.x] = sh[0];
}

// parallel exclusive scan of <=128 block sums
__global__ void k_scan_bsum(int nb) {
    __shared__ int sh[128];
    int t = threadIdx.x;
    int v = (t < nb) ? g_bsum[t] : 0;
    sh[t] = v;
    __syncthreads();
    for (int off = 1; off < 128; off <<= 1) {
        int u = (t >= off) ? sh[t - off] : 0;
        __syncthreads();
        sh[t] += u;
        __syncthreads();
    }
    if (t < nb) g_bsum[t] = sh[t] - v;
}

__global__ void k_scan_blocks(int n, int e_total) {
    __shared__ int sh[1024];
    int i = blockIdx.x * 1024 + threadIdx.x;
    int v = (i < n) ? g_deg[i] : 0;
    sh[threadIdx.x] = v;
    __syncthreads();
    for (int off = 1; off < 1024; off <<= 1) {
        int t = 0;
        if ((int)threadIdx.x >= off) t = sh[threadIdx.x - off];
        __syncthreads();
        sh[threadIdx.x] += t;
        __syncthreads();
    }
    int excl = sh[threadIdx.x] - v;
    if (i < n) {
        int r = excl + g_bsum[blockIdx.x];
        g_rowptr[i] = r;
        g_cursor[i] = r;
    }
    if (i == 0) g_rowptr[n] = e_total;
}

// scatter into CSR by dst; fold coef accumulation (sum over src)
__global__ void k_scatter(const int* __restrict__ src, const int* __restrict__ dst, int e) {
    int i = blockIdx.x * blockDim.x + threadIdx.x;
    if (i < e) {
        int s = src[i];
        int d = dst[i];
        int p = atomicAdd(&g_cursor[d], 1);
        g_col[p] = s;
        atomicAdd(&g_coef[s], g_dis[d]);
    }
}

// ------------------------ bf16 split tensor-core GEMM ----------------------
// h'[M,256] = (A[M,256] @ B[256,256]) * dis[row], stored bf16.
// Block 128x128 (grid.y=2), BK=16, 8 warps (4x2), warp tile 32x64.
// v = hi + lo (both bf16); D += Ah*Bh + Al*Bh + Ah*Bl  (m16n8k16 atoms).

#define AS 24    // A smem row stride (bf16 elems): conflict-free for ldmatrix
#define BSTR 136 // B smem row stride

__device__ __forceinline__ uint32_t smem_u32(const void* p) {
    return (uint32_t)__cvta_generic_to_shared(p);
}

__device__ __forceinline__ void ldsm4(uint32_t* r, uint32_t a) {
    asm volatile("ldmatrix.sync.aligned.m8n8.x4.shared.b16 {%0,%1,%2,%3}, [%4];"
                 : "=r"(r[0]), "=r"(r[1]), "=r"(r[2]), "=r"(r[3]) : "r"(a));
}

__device__ __forceinline__ void ldsm4t(uint32_t* r, uint32_t a) {
    asm volatile("ldmatrix.sync.aligned.m8n8.x4.trans.shared.b16 {%0,%1,%2,%3}, [%4];"
                 : "=r"(r[0]), "=r"(r[1]), "=r"(r[2]), "=r"(r[3]) : "r"(a));
}

__device__ __forceinline__ void mma_bf16(float* d, const uint32_t* a, uint32_t b0, uint32_t b1) {
    asm volatile(
        "mma.sync.aligned.m16n8k16.row.col.f32.bf16.bf16.f32 "
        "{%0,%1,%2,%3}, {%4,%5,%6,%7}, {%8,%9}, {%0,%1,%2,%3};"
        : "+f"(d[0]), "+f"(d[1]), "+f"(d[2]), "+f"(d[3])
        : "r"(a[0]), "r"(a[1]), "r"(a[2]), "r"(a[3]), "r"(b0), "r"(b1));
}

// split float4 -> two bf16x2 hi words + two bf16x2 lo words
__device__ __forceinline__ void split4(float4 v, uint32_t& h0, uint32_t& h1,
                                       uint32_t& l0, uint32_t& l1) {
    __nv_bfloat162 a = __floats2bfloat162_rn(v.x, v.y);
    __nv_bfloat162 b = __floats2bfloat162_rn(v.z, v.w);
    float rx = v.x - __bfloat162float(a.x);
    float ry = v.y - __bfloat162float(a.y);
    float rz = v.z - __bfloat162float(b.x);
    float rw = v.w - __bfloat162float(b.y);
    __nv_bfloat162 c = __floats2bfloat162_rn(rx, ry);
    __nv_bfloat162 d = __floats2bfloat162_rn(rz, rw);
    h0 = *(uint32_t*)&a; h1 = *(uint32_t*)&b;
    l0 = *(uint32_t*)&c; l1 = *(uint32_t*)&d;
}

__global__ __launch_bounds__(256, 2)
void k_gemm_bf16(const float* __restrict__ A, const float* __restrict__ B, int M) {
    __shared__ __nv_bfloat16 Ah[128 * AS], Al[128 * AS];
    __shared__ __nv_bfloat16 Bh[16 * BSTR], Bl[16 * BSTR];

    int tid = threadIdx.x;
    int bm = blockIdx.x * 128;
    int bn = blockIdx.y * 128;
    int wid = tid >> 5;
    int lane = tid & 31;
    int wm = (wid & 3) * 32;
    int wn = (wid >> 2) * 64;
    int qr = lane >> 2, qc = lane & 3;

    // per-thread global load coords (2 float4 each for A and B per tile)
    int ar0 = (tid + 0) >> 2, ac0 = ((tid + 0) & 3) << 2;
    int ar1 = (tid + 256) >> 2, ac1 = ((tid + 256) & 3) << 2;
    int bk0 = (tid + 0) >> 5, bn0 = ((tid + 0) & 31) << 2;
    int bk1 = (tid + 256) >> 5, bn1 = ((tid + 256) & 31) << 2;

    // ldmatrix lane addresses
    int la = lane & 15, lb = lane >> 4;
    uint32_t adAh = smem_u32(Ah) + (uint32_t)(((wm + la) * AS + lb * 8) * 2);
    uint32_t adAl = smem_u32(Al) + (uint32_t)(((wm + la) * AS + lb * 8) * 2);
    uint32_t adBh = smem_u32(Bh) + (uint32_t)((la * BSTR + wn + lb * 8) * 2);
    uint32_t adBl = smem_u32(Bl) + (uint32_t)((la * BSTR + wn + lb * 8) * 2);

    float d[2][8][4];
#pragma unroll
    for (int i = 0; i < 2; i++)
#pragma unroll
        for (int j = 0; j < 8; j++)
#pragma unroll
            for (int q = 0; q < 4; q++) d[i][j][q] = 0.0f;

    float4 pa0, pa1, pb0, pb1;
    {
        int g0 = bm + ar0, g1 = bm + ar1;
        pa0 = (g0 < M) ? *(const float4*)(A + (size_t)g0 * 256 + ac0) : make_float4(0.f, 0.f, 0.f, 0.f);
        pa1 = (g1 < M) ? *(const float4*)(A + (size_t)g1 * 256 + ac1) : make_float4(0.f, 0.f, 0.f, 0.f);
        pb0 = *(const float4*)(B + (size_t)bk0 * 256 + bn + bn0);
        pb1 = *(const float4*)(B + (size_t)bk1 * 256 + bn + bn1);
    }

    for (int t8 = 0; t8 < 16; t8++) {
        // STS current regs (split hi/lo)
        {
            uint32_t h0, h1, l0, l1;
            split4(pa0, h0, h1, l0, l1);
            *(uint2*)&Ah[ar0 * AS + ac0] = make_uint2(h0, h1);
            *(uint2*)&Al[ar0 * AS + ac0] = make_uint2(l0, l1);
            split4(pa1, h0, h1, l0, l1);
            *(uint2*)&Ah[ar1 * AS + ac1] = make_uint2(h0, h1);
            *(uint2*)&Al[ar1 * AS + ac1] = make_uint2(l0, l1);
            split4(pb0, h0, h1, l0, l1);
            *(uint2*)&Bh[bk0 * BSTR + bn0] = make_uint2(h0, h1);
            *(uint2*)&Bl[bk0 * BSTR + bn0] = make_uint2(l0, l1);
            split4(pb1, h0, h1, l0, l1);
            *(uint2*)&Bh[bk1 * BSTR + bn1] = make_uint2(h0, h1);
            *(uint2*)&Bl[bk1 * BSTR + bn1] = make_uint2(l0, l1);
        }
        __syncthreads();

        // prefetch next tile
        if (t8 < 15) {
            int k0 = (t8 + 1) * 16;
            int g0 = bm + ar0, g1 = bm + ar1;
            pa0 = (g0 < M) ? *(const float4*)(A + (size_t)g0 * 256 + k0 + ac0) : make_float4(0.f, 0.f, 0.f, 0.f);
            pa1 = (g1 < M) ? *(const float4*)(A + (size_t)g1 * 256 + k0 + ac1) : make_float4(0.f, 0.f, 0.f, 0.f);
            pb0 = *(const float4*)(B + (size_t)(k0 + bk0) * 256 + bn + bn0);
            pb1 = *(const float4*)(B + (size_t)(k0 + bk1) * 256 + bn + bn1);
        }

        // compute
        {
            uint32_t ah0[4], ah1[4], al0[4], al1[4];
            ldsm4(ah0, adAh);
            ldsm4(ah1, adAh + 16 * AS * 2);
            ldsm4(al0, adAl);
            ldsm4(al1, adAl + 16 * AS * 2);
#pragma unroll
            for (int t = 0; t < 4; t++) {
                uint32_t bh[4], bl[4];
                ldsm4t(bh, adBh + t * 32);
                ldsm4t(bl, adBl + t * 32);
                mma_bf16(d[0][2 * t],     ah0, bh[0], bh[1]);
                mma_bf16(d[1][2 * t],     ah1, bh[0], bh[1]);
                mma_bf16(d[0][2 * t + 1], ah0, bh[2], bh[3]);
                mma_bf16(d[1][2 * t + 1], ah1, bh[2], bh[3]);
                mma_bf16(d[0][2 * t],     al0, bh[0], bh[1]);
                mma_bf16(d[1][2 * t],     al1, bh[0], bh[1]);
                mma_bf16(d[0][2 * t + 1], al0, bh[2], bh[3]);
                mma_bf16(d[1][2 * t + 1], al1, bh[2], bh[3]);
                mma_bf16(d[0][2 * t],     ah0, bl[0], bl[1]);
                mma_bf16(d[1][2 * t],     ah1, bl[0], bl[1]);
                mma_bf16(d[0][2 * t + 1], ah0, bl[2], bl[3]);
                mma_bf16(d[1][2 * t + 1], ah1, bl[2], bl[3]);
            }
        }
        __syncthreads();
    }

    // epilogue: * dis[row], bf16 store
#pragma unroll
    for (int ma = 0; ma < 2; ma++) {
        int r0 = bm + wm + 16 * ma + qr;
        int r1 = r0 + 8;
        float w0 = (r0 < M) ? g_dis[r0] : 0.0f;
        float w1 = (r1 < M) ? g_dis[r1] : 0.0f;
#pragma unroll
        for (int na = 0; na < 8; na++) {
            int c = bn + wn + 8 * na + 2 * qc;
            if (r0 < M) {
                __nv_bfloat162 p = __floats2bfloat162_rn(d[ma][na][0] * w0, d[ma][na][1] * w0);
                *(__nv_bfloat162*)(&g_hb[(size_t)r0 * 256 + c]) = p;
            }
            if (r1 < M) {
                __nv_bfloat162 p = __floats2bfloat162_rn(d[ma][na][2] * w1, d[ma][na][3] * w1);
                *(__nv_bfloat162*)(&g_hb[(size_t)r1 * 256 + c]) = p;
            }
        }
    }
}

// -------------------- fused aggregation + weighted reduce -------------------

__device__ __forceinline__ void add8(float* acc, uint4 v) {
    acc[0] += __uint_as_float(v.x << 16);
    acc[1] += __uint_as_float(v.x & 0xffff0000u);
    acc[2] += __uint_as_float(v.y << 16);
    acc[3] += __uint_as_float(v.y & 0xffff0000u);
    acc[4] += __uint_as_float(v.z << 16);
    acc[5] += __uint_as_float(v.z & 0xffff0000u);
    acc[6] += __uint_as_float(v.w << 16);
    acc[7] += __uint_as_float(v.w & 0xffff0000u);
}

__global__ __launch_bounds__(256)
void k_agg_fused(const float* __restrict__ bias, int n) {
    __shared__ float sh[8][256];

    int lane = threadIdx.x & 31;
    int w = threadIdx.x >> 5;
    int i = blockIdx.x * 8 + w;

    const uint4* __restrict__ hp = (const uint4*)g_hb;
    float res[8];
#pragma unroll
    for (int q = 0; q < 8; q++) res[q] = 0.0f;

    if (i < n) {
        int s = g_rowptr[i];
        int t = g_rowptr[i + 1];
        float di = g_dis[i];
        float ci = di * (g_coef[i] + di);

        float acc[8];
        uint4 sv = hp[(size_t)i * 32 + lane];
        acc[0] = __uint_as_float(sv.x << 16);
        acc[1] = __uint_as_float(sv.x & 0xffff0000u);
        acc[2] = __uint_as_float(sv.y << 16);
        acc[3] = __uint_as_float(sv.y & 0xffff0000u);
        acc[4] = __uint_as_float(sv.z << 16);
        acc[5] = __uint_as_float(sv.z & 0xffff0000u);
        acc[6] = __uint_as_float(sv.w << 16);
        acc[7] = __uint_as_float(sv.w & 0xffff0000u);

        for (int base = s; base < t; base += 32) {
            int m = min(32, t - base);
            int jv = (base + lane < t) ? g_col[base + lane] : 0;
#pragma unroll 4
            for (int k = 0; k < m; k++) {
                int j = __shfl_sync(0xffffffffu, jv, k);
                add8(acc, hp[(size_t)j * 32 + lane]);
            }
        }

        float4 b0 = *(const float4*)(bias + lane * 8);
        float4 b1 = *(const float4*)(bias + lane * 8 + 4);
        res[0] = fmaxf(acc[0] * di + b0.x, 0.f) * ci;
        res[1] = fmaxf(acc[1] * di + b0.y, 0.f) * ci;
        res[2] = fmaxf(acc[2] * di + b0.z, 0.f) * ci;
        res[3] = fmaxf(acc[3] * di + b0.w, 0.f) * ci;
        res[4] = fmaxf(acc[4] * di + b1.x, 0.f) * ci;
        res[5] = fmaxf(acc[5] * di + b1.y, 0.f) * ci;
        res[6] = fmaxf(acc[6] * di + b1.z, 0.f) * ci;
        res[7] = fmaxf(acc[7] * di + b1.w, 0.f) * ci;
    }

#pragma unroll
    for (int q = 0; q < 8; q++) sh[w][lane * 8 + q] = res[q];
    __syncthreads();

    int c = threadIdx.x;
    float ssum = 0.0f;
#pragma unroll
    for (int q = 0; q < 8; q++) ssum += sh[q][c];
    g_part[(size_t)blockIdx.x * 256 + c] = ssum;
}

// ------------------------------- reductions --------------------------------

__global__ void k_reduce_stage1(int nb) {
    int c = threadIdx.x;
    int rows_per = (nb + 255) / 256;
    int r0 = blockIdx.x * rows_per;
    int r1 = min(r0 + rows_per, nb);
    float s = 0.0f;
    for (int r = r0; r < r1; r++) s += g_part[(size_t)r * 256 + c];
    g_part2[blockIdx.x * 256 + c] = s;
}

__global__ void k_final(const float* __restrict__ W2, const float* __restrict__ b2,
                        float* __restrict__ out, int n) {
    __shared__ float z[256];
    int c = threadIdx.x;
    float s = 0.0f;
    for (int b = 0; b < 256; b++) s += g_part2[b * 256 + c];
    z[c] = s / (float)n;
    __syncthreads();

    float o = b2[c];
#pragma unroll 8
    for (int k = 0; k < 256; k++) o += z[k] * W2[k * 256 + c];
    out[c] = o;
}

// -------------------------------- launch -----------------------------------

extern "C" void kernel_launch(void* const* d_in, const int* in_sizes, int n_in,
                              void* d_out, int out_size) {
    const float* x  = (const float*)d_in[0];
    const float* W1 = (const float*)d_in[1];
    const float* b1 = (const float*)d_in[2];
    const float* W2 = (const float*)d_in[3];
    const float* b2 = (const float*)d_in[4];
    const int*   ei = (const int*)d_in[5];

    int n = in_sizes[0] / DIM;
    int e = in_sizes[5] / 2;
    const int* src = ei;
    const int* dst = ei + e;
    float* out = (float*)d_out;

    int nb1024 = (n + 1023) / 1024;
    int agg_blocks = (n + 7) / 8;

    // --- CSR build + coefficients ---
    k_zero<<<(n + 255) / 256, 256>>>(n);
    k_count<<<(e + 255) / 256, 256>>>(dst, e);
    k_block_sums<<<nb1024, 256>>>(n);     // also computes dis
    k_scan_bsum<<<1, 128>>>(nb1024);
    k_scan_blocks<<<nb1024, 1024>>>(n, e);
    k_scatter<<<(e + 255) / 256, 256>>>(src, dst, e);  // also accumulates coef

    // --- layer 1 GEMM (bf16 split, tensor cores) ---
    dim3 gemm_grid((n + 127) / 128, 2);
    k_gemm_bf16<<<gemm_grid, 256>>>(x, W1, n);

    // --- fused aggregate + relu + weighted reduce (layer 2 collapsed) ---
    k_agg_fused<<<agg_blocks, 256>>>(b1, n);

    // --- reduce partials, matvec with W2, bias, mean ---
    k_reduce_stage1<<<256, 256>>>(agg_blocks);
    k_final<<<1, 256>>>(W2, b2, out, n);
}

// round 8
// speedup vs baseline: 3.7393x; 1.0117x over previous
#include <cuda_runtime.h>
#include <cuda_bf16.h>
#include <cstdint>

// ---------------------------------------------------------------------------
// GCNEncoder, collapsed form. Layer-1 GEMM = bf16 hi/lo split (3-term) on
// tensor cores with ldmatrix; CSR edge-scatter fused into the GEMM kernel
// tail (overlaps L2-atomic work with tensor work). Edge gather in bf16.
//
// out = (1/n) (sum_j c[j] h1[j]) W2 + b2
//   c[j]  = dis[j] * ( sum_{edges src=j} dis[dst] + dis[j] )
//   h1[i] = relu( dis[i]*(sum_{j in N_in(i)} h'[j] + h'[i]) + b1 )
//   h'[j] = (x W1)[j] * dis[j]   (bf16)
// ---------------------------------------------------------------------------

#define NMAX 100000
#define EMAX 3200000
#define DIM  256
#define AGG_BLOCKS ((NMAX + 7) / 8)

__device__ int   g_deg[NMAX];
__device__ float g_dis[NMAX];
__device__ float g_coef[NMAX];
__device__ int   g_rowptr[NMAX + 1];
__device__ int   g_cursor[NMAX];
__device__ int   g_col[EMAX];
__device__ __align__(16) __nv_bfloat16 g_hb[(size_t)NMAX * DIM];
__device__ float g_part[(size_t)AGG_BLOCKS * DIM];
__device__ float g_part2[256 * DIM];
__device__ int   g_bsum[256];

// ---------------------------- degree / CSR build ---------------------------

__global__ void k_zero(int n) {
    int i = blockIdx.x * blockDim.x + threadIdx.x;
    if (i < n) { g_deg[i] = 0; g_coef[i] = 0.0f; }
}

__global__ void k_count(const int* __restrict__ dst, int e) {
    int i = blockIdx.x * blockDim.x + threadIdx.x;
    if (i < e) atomicAdd(&g_deg[dst[i]], 1);
}

// block TOTALS over 1024-entry chunks; also computes dis = rsqrt(deg+1)
__global__ void k_block_sums(int n) {
    __shared__ int sh[256];
    int base = blockIdx.x * 1024;
    int s = 0;
#pragma unroll
    for (int q = 0; q < 4; q++) {
        int i = base + q * 256 + threadIdx.x;
        if (i < n) {
            int d = g_deg[i];
            s += d;
            g_dis[i] = rsqrtf((float)d + 1.0f);
        }
    }
    sh[threadIdx.x] = s;
    __syncthreads();
    for (int off = 128; off > 0; off >>= 1) {
        if (threadIdx.x < off) sh[threadIdx.x] += sh[threadIdx.x + off];
        __syncthreads();
    }
    if (threadIdx.x == 0) g_bsum[blockIdx.x] = sh[0];
}

// per-block scan; each block derives its global offset by reducing the
// (<=128) preceding block totals itself — no separate scan kernel.
__global__ void k_scan_blocks(int n, int e_total) {
    __shared__ int sh[1024];
    __shared__ int wsum[32];

    // block offset = sum of g_bsum[0..blockIdx.x)
    int pre = (threadIdx.x < blockIdx.x) ? g_bsum[threadIdx.x] : 0;
#pragma unroll
    for (int off = 16; off > 0; off >>= 1)
        pre += __shfl_down_sync(0xffffffffu, pre, off);
    if ((threadIdx.x & 31) == 0) wsum[threadIdx.x >> 5] = pre;
    __syncthreads();
    if (threadIdx.x == 0) {
        int s = 0;
#pragma unroll
        for (int w = 0; w < 32; w++) s += wsum[w];
        wsum[0] = s;
    }
    __syncthreads();
    int blockoff = wsum[0];

    int i = blockIdx.x * 1024 + threadIdx.x;
    int v = (i < n) ? g_deg[i] : 0;
    sh[threadIdx.x] = v;
    __syncthreads();
    for (int off = 1; off < 1024; off <<= 1) {
        int t = 0;
        if ((int)threadIdx.x >= off) t = sh[threadIdx.x - off];
        __syncthreads();
        sh[threadIdx.x] += t;
        __syncthreads();
    }
    int excl = sh[threadIdx.x] - v;
    if (i < n) {
        int r = excl + blockoff;
        g_rowptr[i] = r;
        g_cursor[i] = r;
    }
    if (i == 0) g_rowptr[n] = e_total;
}

// ------------------- bf16 split tensor-core GEMM + scatter -----------------
// h'[M,256] = (A[M,256] @ B[256,256]) * dis[row], stored bf16.
// Block 128x128 (grid.y=2), BK=16, 8 warps (4x2), warp tile 32x64.
// v = hi + lo (both bf16); D += Ah*Bh + Al*Bh + Ah*Bl  (m16n8k16 atoms).
// Tail phase: each block scatters its slice of edges into CSR (+coef atomics),
// overlapping L2-atomic traffic with other blocks' tensor work.

#define AS 24    // A smem row stride (bf16 elems)
#define BSTR 136 // B smem row stride

__device__ __forceinline__ uint32_t smem_u32(const void* p) {
    return (uint32_t)__cvta_generic_to_shared(p);
}

__device__ __forceinline__ void ldsm4(uint32_t* r, uint32_t a) {
    asm volatile("ldmatrix.sync.aligned.m8n8.x4.shared.b16 {%0,%1,%2,%3}, [%4];"
                 : "=r"(r[0]), "=r"(r[1]), "=r"(r[2]), "=r"(r[3]) : "r"(a));
}

__device__ __forceinline__ void ldsm4t(uint32_t* r, uint32_t a) {
    asm volatile("ldmatrix.sync.aligned.m8n8.x4.trans.shared.b16 {%0,%1,%2,%3}, [%4];"
                 : "=r"(r[0]), "=r"(r[1]), "=r"(r[2]), "=r"(r[3]) : "r"(a));
}

__device__ __forceinline__ void mma_bf16(float* d, const uint32_t* a, uint32_t b0, uint32_t b1) {
    asm volatile(
        "mma.sync.aligned.m16n8k16.row.col.f32.bf16.bf16.f32 "
        "{%0,%1,%2,%3}, {%4,%5,%6,%7}, {%8,%9}, {%0,%1,%2,%3};"
        : "+f"(d[0]), "+f"(d[1]), "+f"(d[2]), "+f"(d[3])
        : "r"(a[0]), "r"(a[1]), "r"(a[2]), "r"(a[3]), "r"(b0), "r"(b1));
}

__device__ __forceinline__ void split4(float4 v, uint32_t& h0, uint32_t& h1,
                                       uint32_t& l0, uint32_t& l1) {
    __nv_bfloat162 a = __floats2bfloat162_rn(v.x, v.y);
    __nv_bfloat162 b = __floats2bfloat162_rn(v.z, v.w);
    float rx = v.x - __bfloat162float(a.x);
    float ry = v.y - __bfloat162float(a.y);
    float rz = v.z - __bfloat162float(b.x);
    float rw = v.w - __bfloat162float(b.y);
    __nv_bfloat162 c = __floats2bfloat162_rn(rx, ry);
    __nv_bfloat162 d = __floats2bfloat162_rn(rz, rw);
    h0 = *(uint32_t*)&a; h1 = *(uint32_t*)&b;
    l0 = *(uint32_t*)&c; l1 = *(uint32_t*)&d;
}

__global__ __launch_bounds__(256, 2)
void k_gemm_scatter(const float* __restrict__ A, const float* __restrict__ B, int M,
                    const int* __restrict__ esrc, const int* __restrict__ edst, int E) {
    __shared__ __nv_bfloat16 Ah[128 * AS], Al[128 * AS];
    __shared__ __nv_bfloat16 Bh[16 * BSTR], Bl[16 * BSTR];

    int tid = threadIdx.x;
    int bm = blockIdx.x * 128;
    int bn = blockIdx.y * 128;
    int wid = tid >> 5;
    int lane = tid & 31;
    int wm = (wid & 3) * 32;
    int wn = (wid >> 2) * 64;
    int qr = lane >> 2, qc = lane & 3;

    int ar0 = (tid + 0) >> 2, ac0 = ((tid + 0) & 3) << 2;
    int ar1 = (tid + 256) >> 2, ac1 = ((tid + 256) & 3) << 2;
    int bk0 = (tid + 0) >> 5, bn0 = ((tid + 0) & 31) << 2;
    int bk1 = (tid + 256) >> 5, bn1 = ((tid + 256) & 31) << 2;

    int la = lane & 15, lb = lane >> 4;
    uint32_t adAh = smem_u32(Ah) + (uint32_t)(((wm + la) * AS + lb * 8) * 2);
    uint32_t adAl = smem_u32(Al) + (uint32_t)(((wm + la) * AS + lb * 8) * 2);
    uint32_t adBh = smem_u32(Bh) + (uint32_t)((la * BSTR + wn + lb * 8) * 2);
    uint32_t adBl = smem_u32(Bl) + (uint32_t)((la * BSTR + wn + lb * 8) * 2);

    float d[2][8][4];
#pragma unroll
    for (int i = 0; i < 2; i++)
#pragma unroll
        for (int j = 0; j < 8; j++)
#pragma unroll
            for (int q = 0; q < 4; q++) d[i][j][q] = 0.0f;

    float4 pa0, pa1, pb0, pb1;
    {
        int g0 = bm + ar0, g1 = bm + ar1;
        pa0 = (g0 < M) ? *(const float4*)(A + (size_t)g0 * 256 + ac0) : make_float4(0.f, 0.f, 0.f, 0.f);
        pa1 = (g1 < M) ? *(const float4*)(A + (size_t)g1 * 256 + ac1) : make_float4(0.f, 0.f, 0.f, 0.f);
        pb0 = *(const float4*)(B + (size_t)bk0 * 256 + bn + bn0);
        pb1 = *(const float4*)(B + (size_t)bk1 * 256 + bn + bn1);
    }

    for (int t8 = 0; t8 < 16; t8++) {
        {
            uint32_t h0, h1, l0, l1;
            split4(pa0, h0, h1, l0, l1);
            *(uint2*)&Ah[ar0 * AS + ac0] = make_uint2(h0, h1);
            *(uint2*)&Al[ar0 * AS + ac0] = make_uint2(l0, l1);
            split4(pa1, h0, h1, l0, l1);
            *(uint2*)&Ah[ar1 * AS + ac1] = make_uint2(h0, h1);
            *(uint2*)&Al[ar1 * AS + ac1] = make_uint2(l0, l1);
            split4(pb0, h0, h1, l0, l1);
            *(uint2*)&Bh[bk0 * BSTR + bn0] = make_uint2(h0, h1);
            *(uint2*)&Bl[bk0 * BSTR + bn0] = make_uint2(l0, l1);
            split4(pb1, h0, h1, l0, l1);
            *(uint2*)&Bh[bk1 * BSTR + bn1] = make_uint2(h0, h1);
            *(uint2*)&Bl[bk1 * BSTR + bn1] = make_uint2(l0, l1);
        }
        __syncthreads();

        if (t8 < 15) {
            int k0 = (t8 + 1) * 16;
            int g0 = bm + ar0, g1 = bm + ar1;
            pa0 = (g0 < M) ? *(const float4*)(A + (size_t)g0 * 256 + k0 + ac0) : make_float4(0.f, 0.f, 0.f, 0.f);
            pa1 = (g1 < M) ? *(const float4*)(A + (size_t)g1 * 256 + k0 + ac1) : make_float4(0.f, 0.f, 0.f, 0.f);
            pb0 = *(const float4*)(B + (size_t)(k0 + bk0) * 256 + bn + bn0);
            pb1 = *(const float4*)(B + (size_t)(k0 + bk1) * 256 + bn + bn1);
        }

        {
            uint32_t ah0[4], ah1[4], al0[4], al1[4];
            ldsm4(ah0, adAh);
            ldsm4(ah1, adAh + 16 * AS * 2);
            ldsm4(al0, adAl);
            ldsm4(al1, adAl + 16 * AS * 2);
#pragma unroll
            for (int t = 0; t < 4; t++) {
                uint32_t bh[4], bl[4];
                ldsm4t(bh, adBh + t * 32);
                ldsm4t(bl, adBl + t * 32);
                mma_bf16(d[0][2 * t],     ah0, bh[0], bh[1]);
                mma_bf16(d[1][2 * t],     ah1, bh[0], bh[1]);
                mma_bf16(d[0][2 * t + 1], ah0, bh[2], bh[3]);
                mma_bf16(d[1][2 * t + 1], ah1, bh[2], bh[3]);
                mma_bf16(d[0][2 * t],     al0, bh[0], bh[1]);
                mma_bf16(d[1][2 * t],     al1, bh[0], bh[1]);
                mma_bf16(d[0][2 * t + 1], al0, bh[2], bh[3]);
                mma_bf16(d[1][2 * t + 1], al1, bh[2], bh[3]);
                mma_bf16(d[0][2 * t],     ah0, bl[0], bl[1]);
                mma_bf16(d[1][2 * t],     ah1, bl[0], bl[1]);
                mma_bf16(d[0][2 * t + 1], ah0, bl[2], bl[3]);
                mma_bf16(d[1][2 * t + 1], ah1, bl[2], bl[3]);
            }
        }
        __syncthreads();
    }

    // epilogue: * dis[row], bf16 store
#pragma unroll
    for (int ma = 0; ma < 2; ma++) {
        int r0 = bm + wm + 16 * ma + qr;
        int r1 = r0 + 8;
        float w0 = (r0 < M) ? g_dis[r0] : 0.0f;
        float w1 = (r1 < M) ? g_dis[r1] : 0.0f;
#pragma unroll
        for (int na = 0; na < 8; na++) {
            int c = bn + wn + 8 * na + 2 * qc;
            if (r0 < M) {
                __nv_bfloat162 p = __floats2bfloat162_rn(d[ma][na][0] * w0, d[ma][na][1] * w0);
                *(__nv_bfloat162*)(&g_hb[(size_t)r0 * 256 + c]) = p;
            }
            if (r1 < M) {
                __nv_bfloat162 p = __floats2bfloat162_rn(d[ma][na][2] * w1, d[ma][na][3] * w1);
                *(__nv_bfloat162*)(&g_hb[(size_t)r1 * 256 + c]) = p;
            }
        }
    }

    // ---- tail: scatter this block's slice of edges into CSR (+ coef) ----
    // rowptr/cursor/dis were finalized by earlier kernels in stream order.
    {
        int nblocks = gridDim.x * gridDim.y;
        int bid = blockIdx.y * gridDim.x + blockIdx.x;
        int per = (E + nblocks - 1) / nblocks;
        int e0 = bid * per;
        int e1 = min(e0 + per, E);
        for (int i = e0 + tid; i < e1; i += 256) {
            int s = esrc[i];
            int dd = edst[i];
            int p = atomicAdd(&g_cursor[dd], 1);
            g_col[p] = s;
            atomicAdd(&g_coef[s], g_dis[dd]);
        }
    }
}

// -------------------- fused aggregation + weighted reduce -------------------

__device__ __forceinline__ void add8(float* acc, uint4 v) {
    acc[0] += __uint_as_float(v.x << 16);
    acc[1] += __uint_as_float(v.x & 0xffff0000u);
    acc[2] += __uint_as_float(v.y << 16);
    acc[3] += __uint_as_float(v.y & 0xffff0000u);
    acc[4] += __uint_as_float(v.z << 16);
    acc[5] += __uint_as_float(v.z & 0xffff0000u);
    acc[6] += __uint_as_float(v.w << 16);
    acc[7] += __uint_as_float(v.w & 0xffff0000u);
}

__global__ __launch_bounds__(256)
void k_agg_fused(const float* __restrict__ bias, int n) {
    __shared__ float sh[8][256];

    int lane = threadIdx.x & 31;
    int w = threadIdx.x >> 5;
    int i = blockIdx.x * 8 + w;

    const uint4* __restrict__ hp = (const uint4*)g_hb;
    float res[8];
#pragma unroll
    for (int q = 0; q < 8; q++) res[q] = 0.0f;

    if (i < n) {
        int s = g_rowptr[i];
        int t = g_rowptr[i + 1];
        float di = g_dis[i];
        float ci = di * (g_coef[i] + di);

        float acc[8];
        uint4 sv = hp[(size_t)i * 32 + lane];
        acc[0] = __uint_as_float(sv.x << 16);
        acc[1] = __uint_as_float(sv.x & 0xffff0000u);
        acc[2] = __uint_as_float(sv.y << 16);
        acc[3] = __uint_as_float(sv.y & 0xffff0000u);
        acc[4] = __uint_as_float(sv.z << 16);
        acc[5] = __uint_as_float(sv.z & 0xffff0000u);
        acc[6] = __uint_as_float(sv.w << 16);
        acc[7] = __uint_as_float(sv.w & 0xffff0000u);

        for (int base = s; base < t; base += 32) {
            int m = min(32, t - base);
            int jv = (base + lane < t) ? g_col[base + lane] : 0;
#pragma unroll 4
            for (int k = 0; k < m; k++) {
                int j = __shfl_sync(0xffffffffu, jv, k);
                add8(acc, hp[(size_t)j * 32 + lane]);
            }
        }

        float4 b0 = *(const float4*)(bias + lane * 8);
        float4 b1 = *(const float4*)(bias + lane * 8 + 4);
        res[0] = fmaxf(acc[0] * di + b0.x, 0.f) * ci;
        res[1] = fmaxf(acc[1] * di + b0.y, 0.f) * ci;
        res[2] = fmaxf(acc[2] * di + b0.z, 0.f) * ci;
        res[3] = fmaxf(acc[3] * di + b0.w, 0.f) * ci;
        res[4] = fmaxf(acc[4] * di + b1.x, 0.f) * ci;
        res[5] = fmaxf(acc[5] * di + b1.y, 0.f) * ci;
        res[6] = fmaxf(acc[6] * di + b1.z, 0.f) * ci;
        res[7] = fmaxf(acc[7] * di + b1.w, 0.f) * ci;
    }

#pragma unroll
    for (int q = 0; q < 8; q++) sh[w][lane * 8 + q] = res[q];
    __syncthreads();

    int c = threadIdx.x;
    float ssum = 0.0f;
#pragma unroll
    for (int q = 0; q < 8; q++) ssum += sh[q][c];
    g_part[(size_t)blockIdx.x * 256 + c] = ssum;
}

// ------------------------------- reductions --------------------------------

__global__ void k_reduce_stage1(int nb) {
    int c = threadIdx.x;
    int rows_per = (nb + 255) / 256;
    int r0 = blockIdx.x * rows_per;
    int r1 = min(r0 + rows_per, nb);
    float s = 0.0f;
    for (int r = r0; r < r1; r++) s += g_part[(size_t)r * 256 + c];
    g_part2[blockIdx.x * 256 + c] = s;
}

__global__ void k_final(const float* __restrict__ W2, const float* __restrict__ b2,
                        float* __restrict__ out, int n) {
    __shared__ float z[256];
    int c = threadIdx.x;
    float s = 0.0f;
    for (int b = 0; b < 256; b++) s += g_part2[b * 256 + c];
    z[c] = s / (float)n;
    __syncthreads();

    float o = b2[c];
#pragma unroll 8
    for (int k = 0; k < 256; k++) o += z[k] * W2[k * 256 + c];
    out[c] = o;
}

// -------------------------------- launch -----------------------------------

extern "C" void kernel_launch(void* const* d_in, const int* in_sizes, int n_in,
                              void* d_out, int out_size) {
    const float* x  = (const float*)d_in[0];
    const float* W1 = (const float*)d_in[1];
    const float* b1 = (const float*)d_in[2];
    const float* W2 = (const float*)d_in[3];
    const float* b2 = (const float*)d_in[4];
    const int*   ei = (const int*)d_in[5];

    int n = in_sizes[0] / DIM;
    int e = in_sizes[5] / 2;
    const int* src = ei;
    const int* dst = ei + e;
    float* out = (float*)d_out;

    int nb1024 = (n + 1023) / 1024;
    int agg_blocks = (n + 7) / 8;

    // --- degree / dis / rowptr ---
    k_zero<<<(n + 255) / 256, 256>>>(n);
    k_count<<<(e + 255) / 256, 256>>>(dst, e);
    k_block_sums<<<nb1024, 256>>>(n);          // dis + block totals
    k_scan_blocks<<<nb1024, 1024>>>(n, e);     // rowptr + cursor (self-offset)

    // --- layer-1 GEMM (bf16 split) with fused edge scatter tail ---
    dim3 gemm_grid((n + 127) / 128, 2);
    k_gemm_scatter<<<gemm_grid, 256>>>(x, W1, n, src, dst, e);

    // --- fused aggregate + relu + weighted reduce (layer 2 collapsed) ---
    k_agg_fused<<<agg_blocks, 256>>>(b1, n);

    // --- reduce partials, matvec with W2, bias, mean ---
    k_reduce_stage1<<<256, 256>>>(agg_blocks);
    k_final<<<1, 256>>>(W2, b2, out, n);
}

// round 10
// speedup vs baseline: 4.0251x; 1.0764x over previous
#include <cuda_runtime.h>
#include <cuda_bf16.h>
#include <cuda_fp8.h>
#include <cstdint>

// ---------------------------------------------------------------------------
// GCNEncoder, collapsed form.
//   out = (1/n) (sum_j c[j] h1[j]) W2 + b2
//   c[j]  = dis[j] * ( sum_{edges src=j} dis[dst] + dis[j] )
//   h1[i] = relu( dis[i]*(sum_{j in N_in(i)} h'[j] + h'[i]) + b1 )
//   h'[j] = (x W1)[j] * dis[j]   -- stored e4m3 (fp8): gather is 256B/row,
//                                   L2-resident, half the bf16 traffic.
// Layer-1 GEMM: bf16 hi/lo split (3-term) mma.m16n8k16 + ldmatrix; CSR edge
// scatter fused into the GEMM tail. Aggregation unpacks fp8 via
// cvt.rn.f16x2.e4m3x2 (b16 source!) and accumulates in half2.
// ---------------------------------------------------------------------------

#define NMAX 100000
#define EMAX 3200000
#define DIM  256
#define AGG_BLOCKS ((NMAX + 7) / 8)

__device__ int   g_deg[NMAX];
__device__ float g_dis[NMAX];
__device__ float g_coef[NMAX];
__device__ int   g_rowptr[NMAX + 1];
__device__ int   g_cursor[NMAX];
__device__ int   g_col[EMAX];
__device__ __align__(16) uint8_t g_h8[(size_t)NMAX * DIM];  // h' in e4m3
__device__ float g_part[(size_t)AGG_BLOCKS * DIM];
__device__ float g_part2[256 * DIM];
__device__ int   g_bsum[256];

// ---------------------------- degree / CSR build ---------------------------

__global__ void k_count(const int* __restrict__ dst, int e) {
    int i = blockIdx.x * blockDim.x + threadIdx.x;
    if (i < e) atomicAdd(&g_deg[dst[i]], 1);
}

// block TOTALS over 1024-entry chunks; also computes dis = rsqrt(deg+1)
__global__ void k_block_sums(int n) {
    __shared__ int sh[256];
    int base = blockIdx.x * 1024;
    int s = 0;
#pragma unroll
    for (int q = 0; q < 4; q++) {
        int i = base + q * 256 + threadIdx.x;
        if (i < n) {
            int d = g_deg[i];
            s += d;
            g_dis[i] = rsqrtf((float)d + 1.0f);
        }
    }
    sh[threadIdx.x] = s;
    __syncthreads();
    for (int off = 128; off > 0; off >>= 1) {
        if (threadIdx.x < off) sh[threadIdx.x] += sh[threadIdx.x + off];
        __syncthreads();
    }
    if (threadIdx.x == 0) g_bsum[blockIdx.x] = sh[0];
}

// per-block scan; each block derives its global offset from preceding totals
__global__ void k_scan_blocks(int n, int e_total) {
    __shared__ int sh[1024];
    __shared__ int wsum[32];

    int pre = (threadIdx.x < blockIdx.x) ? g_bsum[threadIdx.x] : 0;
#pragma unroll
    for (int off = 16; off > 0; off >>= 1)
        pre += __shfl_down_sync(0xffffffffu, pre, off);
    if ((threadIdx.x & 31) == 0) wsum[threadIdx.x >> 5] = pre;
    __syncthreads();
    if (threadIdx.x == 0) {
        int s = 0;
#pragma unroll
        for (int w = 0; w < 32; w++) s += wsum[w];
        wsum[0] = s;
    }
    __syncthreads();
    int blockoff = wsum[0];

    int i = blockIdx.x * 1024 + threadIdx.x;
    int v = (i < n) ? g_deg[i] : 0;
    sh[threadIdx.x] = v;
    __syncthreads();
    for (int off = 1; off < 1024; off <<= 1) {
        int t = 0;
        if ((int)threadIdx.x >= off) t = sh[threadIdx.x - off];
        __syncthreads();
        sh[threadIdx.x] += t;
        __syncthreads();
    }
    int excl = sh[threadIdx.x] - v;
    if (i < n) {
        int r = excl + blockoff;
        g_rowptr[i] = r;
        g_cursor[i] = r;
    }
    if (i == 0) g_rowptr[n] = e_total;
}

// ------------------- bf16 split tensor-core GEMM + scatter -----------------

#define AS 24
#define BSTR 136

__device__ __forceinline__ uint32_t smem_u32(const void* p) {
    return (uint32_t)__cvta_generic_to_shared(p);
}

__device__ __forceinline__ void ldsm4(uint32_t* r, uint32_t a) {
    asm volatile("ldmatrix.sync.aligned.m8n8.x4.shared.b16 {%0,%1,%2,%3}, [%4];"
                 : "=r"(r[0]), "=r"(r[1]), "=r"(r[2]), "=r"(r[3]) : "r"(a));
}

__device__ __forceinline__ void ldsm4t(uint32_t* r, uint32_t a) {
    asm volatile("ldmatrix.sync.aligned.m8n8.x4.trans.shared.b16 {%0,%1,%2,%3}, [%4];"
                 : "=r"(r[0]), "=r"(r[1]), "=r"(r[2]), "=r"(r[3]) : "r"(a));
}

__device__ __forceinline__ void mma_bf16(float* d, const uint32_t* a, uint32_t b0, uint32_t b1) {
    asm volatile(
        "mma.sync.aligned.m16n8k16.row.col.f32.bf16.bf16.f32 "
        "{%0,%1,%2,%3}, {%4,%5,%6,%7}, {%8,%9}, {%0,%1,%2,%3};"
        : "+f"(d[0]), "+f"(d[1]), "+f"(d[2]), "+f"(d[3])
        : "r"(a[0]), "r"(a[1]), "r"(a[2]), "r"(a[3]), "r"(b0), "r"(b1));
}

__device__ __forceinline__ void split4(float4 v, uint32_t& h0, uint32_t& h1,
                                       uint32_t& l0, uint32_t& l1) {
    __nv_bfloat162 a = __floats2bfloat162_rn(v.x, v.y);
    __nv_bfloat162 b = __floats2bfloat162_rn(v.z, v.w);
    float rx = v.x - __bfloat162float(a.x);
    float ry = v.y - __bfloat162float(a.y);
    float rz = v.z - __bfloat162float(b.x);
    float rw = v.w - __bfloat162float(b.y);
    __nv_bfloat162 c = __floats2bfloat162_rn(rx, ry);
    __nv_bfloat162 d = __floats2bfloat162_rn(rz, rw);
    h0 = *(uint32_t*)&a; h1 = *(uint32_t*)&b;
    l0 = *(uint32_t*)&c; l1 = *(uint32_t*)&d;
}

// pack two f32 into e4m3x2 (result .b16; first PTX src packs the high byte)
__device__ __forceinline__ uint16_t f2e4m3x2(float a, float b) {
    uint16_t r;
    asm("cvt.rn.satfinite.e4m3x2.f32 %0, %1, %2;" : "=h"(r) : "f"(b), "f"(a));
    return r;
}

__global__ __launch_bounds__(256, 2)
void k_gemm_scatter(const float* __restrict__ A, const float* __restrict__ B, int M,
                    const int* __restrict__ esrc, const int* __restrict__ edst, int E) {
    __shared__ __nv_bfloat16 Ah[128 * AS], Al[128 * AS];
    __shared__ __nv_bfloat16 Bh[16 * BSTR], Bl[16 * BSTR];

    int tid = threadIdx.x;
    int bm = blockIdx.x * 128;
    int bn = blockIdx.y * 128;
    int wid = tid >> 5;
    int lane = tid & 31;
    int wm = (wid & 3) * 32;
    int wn = (wid >> 2) * 64;
    int qr = lane >> 2, qc = lane & 3;

    int ar0 = (tid + 0) >> 2, ac0 = ((tid + 0) & 3) << 2;
    int ar1 = (tid + 256) >> 2, ac1 = ((tid + 256) & 3) << 2;
    int bk0 = (tid + 0) >> 5, bn0 = ((tid + 0) & 31) << 2;
    int bk1 = (tid + 256) >> 5, bn1 = ((tid + 256) & 31) << 2;

    int la = lane & 15, lb = lane >> 4;
    uint32_t adAh = smem_u32(Ah) + (uint32_t)(((wm + la) * AS + lb * 8) * 2);
    uint32_t adAl = smem_u32(Al) + (uint32_t)(((wm + la) * AS + lb * 8) * 2);
    uint32_t adBh = smem_u32(Bh) + (uint32_t)((la * BSTR + wn + lb * 8) * 2);
    uint32_t adBl = smem_u32(Bl) + (uint32_t)((la * BSTR + wn + lb * 8) * 2);

    float d[2][8][4];
#pragma unroll
    for (int i = 0; i < 2; i++)
#pragma unroll
        for (int j = 0; j < 8; j++)
#pragma unroll
            for (int q = 0; q < 4; q++) d[i][j][q] = 0.0f;

    float4 pa0, pa1, pb0, pb1;
    {
        int g0 = bm + ar0, g1 = bm + ar1;
        pa0 = (g0 < M) ? *(const float4*)(A + (size_t)g0 * 256 + ac0) : make_float4(0.f, 0.f, 0.f, 0.f);
        pa1 = (g1 < M) ? *(const float4*)(A + (size_t)g1 * 256 + ac1) : make_float4(0.f, 0.f, 0.f, 0.f);
        pb0 = *(const float4*)(B + (size_t)bk0 * 256 + bn + bn0);
        pb1 = *(const float4*)(B + (size_t)bk1 * 256 + bn + bn1);
    }

    for (int t8 = 0; t8 < 16; t8++) {
        {
            uint32_t h0, h1, l0, l1;
            split4(pa0, h0, h1, l0, l1);
            *(uint2*)&Ah[ar0 * AS + ac0] = make_uint2(h0, h1);
            *(uint2*)&Al[ar0 * AS + ac0] = make_uint2(l0, l1);
            split4(pa1, h0, h1, l0, l1);
            *(uint2*)&Ah[ar1 * AS + ac1] = make_uint2(h0, h1);
            *(uint2*)&Al[ar1 * AS + ac1] = make_uint2(l0, l1);
            split4(pb0, h0, h1, l0, l1);
            *(uint2*)&Bh[bk0 * BSTR + bn0] = make_uint2(h0, h1);
            *(uint2*)&Bl[bk0 * BSTR + bn0] = make_uint2(l0, l1);
            split4(pb1, h0, h1, l0, l1);
            *(uint2*)&Bh[bk1 * BSTR + bn1] = make_uint2(h0, h1);
            *(uint2*)&Bl[bk1 * BSTR + bn1] = make_uint2(l0, l1);
        }
        __syncthreads();

        if (t8 < 15) {
            int k0 = (t8 + 1) * 16;
            int g0 = bm + ar0, g1 = bm + ar1;
            pa0 = (g0 < M) ? *(const float4*)(A + (size_t)g0 * 256 + k0 + ac0) : make_float4(0.f, 0.f, 0.f, 0.f);
            pa1 = (g1 < M) ? *(const float4*)(A + (size_t)g1 * 256 + k0 + ac1) : make_float4(0.f, 0.f, 0.f, 0.f);
            pb0 = *(const float4*)(B + (size_t)(k0 + bk0) * 256 + bn + bn0);
            pb1 = *(const float4*)(B + (size_t)(k0 + bk1) * 256 + bn + bn1);
        }

        {
            uint32_t ah0[4], ah1[4], al0[4], al1[4];
            ldsm4(ah0, adAh);
            ldsm4(ah1, adAh + 16 * AS * 2);
            ldsm4(al0, adAl);
            ldsm4(al1, adAl + 16 * AS * 2);
#pragma unroll
            for (int t = 0; t < 4; t++) {
                uint32_t bh[4], bl[4];
                ldsm4t(bh, adBh + t * 32);
                ldsm4t(bl, adBl + t * 32);
                mma_bf16(d[0][2 * t],     ah0, bh[0], bh[1]);
                mma_bf16(d[1][2 * t],     ah1, bh[0], bh[1]);
                mma_bf16(d[0][2 * t + 1], ah0, bh[2], bh[3]);
                mma_bf16(d[1][2 * t + 1], ah1, bh[2], bh[3]);
                mma_bf16(d[0][2 * t],     al0, bh[0], bh[1]);
                mma_bf16(d[1][2 * t],     al1, bh[0], bh[1]);
                mma_bf16(d[0][2 * t + 1], al0, bh[2], bh[3]);
                mma_bf16(d[1][2 * t + 1], al1, bh[2], bh[3]);
                mma_bf16(d[0][2 * t],     ah0, bl[0], bl[1]);
                mma_bf16(d[1][2 * t],     ah1, bl[0], bl[1]);
                mma_bf16(d[0][2 * t + 1], ah0, bl[2], bl[3]);
                mma_bf16(d[1][2 * t + 1], ah1, bl[2], bl[3]);
            }
        }
        __syncthreads();
    }

    // epilogue: * dis[row], convert to e4m3 pairs, 2B stores
#pragma unroll
    for (int ma = 0; ma < 2; ma++) {
        int r0 = bm + wm + 16 * ma + qr;
        int r1 = r0 + 8;
        float w0 = (r0 < M) ? g_dis[r0] : 0.0f;
        float w1 = (r1 < M) ? g_dis[r1] : 0.0f;
#pragma unroll
        for (int na = 0; na < 8; na++) {
            int c = bn + wn + 8 * na + 2 * qc;
            if (r0 < M) {
                uint16_t p = f2e4m3x2(d[ma][na][0] * w0, d[ma][na][1] * w0);
                *(uint16_t*)(&g_h8[(size_t)r0 * 256 + c]) = p;
            }
            if (r1 < M) {
                uint16_t p = f2e4m3x2(d[ma][na][2] * w1, d[ma][na][3] * w1);
                *(uint16_t*)(&g_h8[(size_t)r1 * 256 + c]) = p;
            }
        }
    }

    // ---- tail: scatter this block's slice of edges into CSR (+ coef) ----
    {
        int nblocks = gridDim.x * gridDim.y;
        int bid = blockIdx.y * gridDim.x + blockIdx.x;
        int per = (E + nblocks - 1) / nblocks;
        int e0 = bid * per;
        int e1 = min(e0 + per, E);
        for (int i = e0 + tid; i < e1; i += 256) {
            int s = esrc[i];
            int dd = edst[i];
            int p = atomicAdd(&g_cursor[dd], 1);
            g_col[p] = s;
            atomicAdd(&g_coef[s], g_dis[dd]);
        }
    }
}

// -------------------- fused aggregation + weighted reduce -------------------
// 8 rows / block (one warp per row). Lane l owns cols l*8..l*8+7 = one uint2
// of 8 e4m3. Unpack via cvt.rn.f16x2.e4m3x2 (source is .b16 / "h"!);
// accumulate in half2 (4 HADD2/edge/lane).

__device__ __forceinline__ __half2 e8_to_h2(uint16_t w) {
    uint32_t r;
    asm("cvt.rn.f16x2.e4m3x2 %0, %1;" : "=r"(r) : "h"(w));
    return *(__half2*)&r;
}

__global__ __launch_bounds__(256)
void k_agg_fused(const float* __restrict__ bias, int n) {
    __shared__ float sh[8][256];

    int lane = threadIdx.x & 31;
    int w = threadIdx.x >> 5;
    int i = blockIdx.x * 8 + w;

    const uint2* __restrict__ hp = (const uint2*)g_h8;  // row = 32 uint2
    float res[8];
#pragma unroll
    for (int q = 0; q < 8; q++) res[q] = 0.0f;

    if (i < n) {
        int s = g_rowptr[i];
        int t = g_rowptr[i + 1];
        float di = g_dis[i];
        float ci = di * (g_coef[i] + di);

        // half2 accumulators, initialized with the self-loop row
        __half2 acc[4];
        {
            uint2 sv = hp[(size_t)i * 32 + lane];
            acc[0] = e8_to_h2((uint16_t)(sv.x & 0xffffu));
            acc[1] = e8_to_h2((uint16_t)(sv.x >> 16));
            acc[2] = e8_to_h2((uint16_t)(sv.y & 0xffffu));
            acc[3] = e8_to_h2((uint16_t)(sv.y >> 16));
        }

        for (int base = s; base < t; base += 32) {
            int m = min(32, t - base);
            int jv = (base + lane < t) ? g_col[base + lane] : 0;
#pragma unroll 4
            for (int k = 0; k < m; k++) {
                int j = __shfl_sync(0xffffffffu, jv, k);
                uint2 v = hp[(size_t)j * 32 + lane];
                acc[0] = __hadd2(acc[0], e8_to_h2((uint16_t)(v.x & 0xffffu)));
                acc[1] = __hadd2(acc[1], e8_to_h2((uint16_t)(v.x >> 16)));
                acc[2] = __hadd2(acc[2], e8_to_h2((uint16_t)(v.y & 0xffffu)));
                acc[3] = __hadd2(acc[3], e8_to_h2((uint16_t)(v.y >> 16)));
            }
        }

        float4 b0 = *(const float4*)(bias + lane * 8);
        float4 b1 = *(const float4*)(bias + lane * 8 + 4);
        float2 f0 = __half22float2(acc[0]);
        float2 f1 = __half22float2(acc[1]);
        float2 f2 = __half22float2(acc[2]);
        float2 f3 = __half22float2(acc[3]);
        res[0] = fmaxf(f0.x * di + b0.x, 0.f) * ci;
        res[1] = fmaxf(f0.y * di + b0.y, 0.f) * ci;
        res[2] = fmaxf(f1.x * di + b0.z, 0.f) * ci;
        res[3] = fmaxf(f1.y * di + b0.w, 0.f) * ci;
        res[4] = fmaxf(f2.x * di + b1.x, 0.f) * ci;
        res[5] = fmaxf(f2.y * di + b1.y, 0.f) * ci;
        res[6] = fmaxf(f3.x * di + b1.z, 0.f) * ci;
        res[7] = fmaxf(f3.y * di + b1.w, 0.f) * ci;
    }

#pragma unroll
    for (int q = 0; q < 8; q++) sh[w][lane * 8 + q] = res[q];
    __syncthreads();

    int c = threadIdx.x;
    float ssum = 0.0f;
#pragma unroll
    for (int q = 0; q < 8; q++) ssum += sh[q][c];
    g_part[(size_t)blockIdx.x * 256 + c] = ssum;
}

// ------------------------------- reductions --------------------------------

__global__ void k_reduce_stage1(int nb) {
    int c = threadIdx.x;
    int rows_per = (nb + 255) / 256;
    int r0 = blockIdx.x * rows_per;
    int r1 = min(r0 + rows_per, nb);
    float s = 0.0f;
    for (int r = r0; r < r1; r++) s += g_part[(size_t)r * 256 + c];
    g_part2[blockIdx.x * 256 + c] = s;
}

__global__ void k_final(const float* __restrict__ W2, const float* __restrict__ b2,
                        float* __restrict__ out, int n) {
    __shared__ float z[256];
    int c = threadIdx.x;
    float s = 0.0f;
    for (int b = 0; b < 256; b++) s += g_part2[b * 256 + c];
    z[c] = s / (float)n;
    __syncthreads();

    float o = b2[c];
#pragma unroll 8
    for (int k = 0; k < 256; k++) o += z[k] * W2[k * 256 + c];
    out[c] = o;
}

// -------------------------------- launch -----------------------------------

extern "C" void kernel_launch(void* const* d_in, const int* in_sizes, int n_in,
                              void* d_out, int out_size) {
    const float* x  = (const float*)d_in[0];
    const float* W1 = (const float*)d_in[1];
    const float* b1 = (const float*)d_in[2];
    const float* W2 = (const float*)d_in[3];
    const float* b2 = (const float*)d_in[4];
    const int*   ei = (const int*)d_in[5];

    int n = in_sizes[0] / DIM;
    int e = in_sizes[5] / 2;
    const int* src = ei;
    const int* dst = ei + e;
    float* out = (float*)d_out;

    int nb1024 = (n + 1023) / 1024;
    int agg_blocks = (n + 7) / 8;

    // zero deg/coef via memset nodes (not kernel launches)
    void* p_deg;
    void* p_coef;
    cudaGetSymbolAddress(&p_deg, g_deg);
    cudaGetSymbolAddress(&p_coef, g_coef);
    cudaMemsetAsync(p_deg, 0, (size_t)n * sizeof(int));
    cudaMemsetAsync(p_coef, 0, (size_t)n * sizeof(float));

    // --- degree / dis / rowptr ---
    k_count<<<(e + 255) / 256, 256>>>(dst, e);
    k_block_sums<<<nb1024, 256>>>(n);          // dis + block totals
    k_scan_blocks<<<nb1024, 1024>>>(n, e);     // rowptr + cursor

    // --- layer-1 GEMM (bf16 split) with fused edge scatter tail ---
    dim3 gemm_grid((n + 127) / 128, 2);
    k_gemm_scatter<<<gemm_grid, 256>>>(x, W1, n, src, dst, e);

    // --- fused aggregate + relu + weighted reduce (layer 2 collapsed) ---
    k_agg_fused<<<agg_blocks, 256>>>(b1, n);

    // --- reduce partials, matvec with W2, bias, mean ---
    k_reduce_stage1<<<256, 256>>>(agg_blocks);
    k_final<<<1, 256>>>(W2, b2, out, n);
}

// round 11
// speedup vs baseline: 4.4123x; 1.0962x over previous
#include <cuda_runtime.h>
#include <cuda_bf16.h>
#include <cuda_fp8.h>
#include <cstdint>

// ---------------------------------------------------------------------------
// GCNEncoder, collapsed form.
//   out = (1/n) (sum_j c[j] h1[j]) W2 + b2
//   c[j]  = dis[j] * ( sum_{edges src=j} dis[dst] + dis[j] )
//   h1[i] = relu( dis[i]*(sum_{j in N_in(i)} h'[j] + h'[i]) + b1 )
//   h'[j] = (x W1)[j] * dis[j]   -- stored e4m3; gather is 256B/row (L2-res).
// Layer-1 GEMM: single-term bf16 mma.m16n8k16 (h' is quantized to fp8 anyway,
// so bf16 input rounding (2^-8) is far below the fp8 storage error (2^-4)).
// CSR edge-scatter fused into the GEMM tail.
// ---------------------------------------------------------------------------

#define NMAX 100000
#define EMAX 3200000
#define DIM  256
#define AGG_BLOCKS ((NMAX + 7) / 8)

__device__ int   g_deg[NMAX];
__device__ float g_dis[NMAX];
__device__ float g_coef[NMAX];
__device__ int   g_rowptr[NMAX + 1];
__device__ int   g_cursor[NMAX];
__device__ int   g_col[EMAX];
__device__ __align__(16) uint8_t g_h8[(size_t)NMAX * DIM];  // h' in e4m3
__device__ float g_part[(size_t)AGG_BLOCKS * DIM];
__device__ float g_part2[256 * DIM];
__device__ int   g_bsum[256];

// ---------------------------- degree / CSR build ---------------------------

__global__ void k_count(const int* __restrict__ dst, int e) {
    int i = blockIdx.x * blockDim.x + threadIdx.x;
    if (i < e) atomicAdd(&g_deg[dst[i]], 1);
}

// block TOTALS over 1024-entry chunks; also computes dis = rsqrt(deg+1)
__global__ void k_block_sums(int n) {
    __shared__ int sh[256];
    int base = blockIdx.x * 1024;
    int s = 0;
#pragma unroll
    for (int q = 0; q < 4; q++) {
        int i = base + q * 256 + threadIdx.x;
        if (i < n) {
            int d = g_deg[i];
            s += d;
            g_dis[i] = rsqrtf((float)d + 1.0f);
        }
    }
    sh[threadIdx.x] = s;
    __syncthreads();
    for (int off = 128; off > 0; off >>= 1) {
        if (threadIdx.x < off) sh[threadIdx.x] += sh[threadIdx.x + off];
        __syncthreads();
    }
    if (threadIdx.x == 0) g_bsum[blockIdx.x] = sh[0];
}

// per-block scan; each block derives its global offset from preceding totals
__global__ void k_scan_blocks(int n, int e_total) {
    __shared__ int sh[1024];
    __shared__ int wsum[32];

    int pre = (threadIdx.x < blockIdx.x) ? g_bsum[threadIdx.x] : 0;
#pragma unroll
    for (int off = 16; off > 0; off >>= 1)
        pre += __shfl_down_sync(0xffffffffu, pre, off);
    if ((threadIdx.x & 31) == 0) wsum[threadIdx.x >> 5] = pre;
    __syncthreads();
    if (threadIdx.x == 0) {
        int s = 0;
#pragma unroll
        for (int w = 0; w < 32; w++) s += wsum[w];
        wsum[0] = s;
    }
    __syncthreads();
    int blockoff = wsum[0];

    int i = blockIdx.x * 1024 + threadIdx.x;
    int v = (i < n) ? g_deg[i] : 0;
    sh[threadIdx.x] = v;
    __syncthreads();
    for (int off = 1; off < 1024; off <<= 1) {
        int t = 0;
        if ((int)threadIdx.x >= off) t = sh[threadIdx.x - off];
        __syncthreads();
        sh[threadIdx.x] += t;
        __syncthreads();
    }
    int excl = sh[threadIdx.x] - v;
    if (i < n) {
        int r = excl + blockoff;
        g_rowptr[i] = r;
        g_cursor[i] = r;
    }
    if (i == 0) g_rowptr[n] = e_total;
}

// ---------------- single-term bf16 tensor-core GEMM + scatter ---------------
// Block 128x128 (grid.y=2), BK=16, 8 warps (4x2), warp tile 32x64.

#define AS 24
#define BSTR 136

__device__ __forceinline__ uint32_t smem_u32(const void* p) {
    return (uint32_t)__cvta_generic_to_shared(p);
}

__device__ __forceinline__ void ldsm4(uint32_t* r, uint32_t a) {
    asm volatile("ldmatrix.sync.aligned.m8n8.x4.shared.b16 {%0,%1,%2,%3}, [%4];"
                 : "=r"(r[0]), "=r"(r[1]), "=r"(r[2]), "=r"(r[3]) : "r"(a));
}

__device__ __forceinline__ void ldsm4t(uint32_t* r, uint32_t a) {
    asm volatile("ldmatrix.sync.aligned.m8n8.x4.trans.shared.b16 {%0,%1,%2,%3}, [%4];"
                 : "=r"(r[0]), "=r"(r[1]), "=r"(r[2]), "=r"(r[3]) : "r"(a));
}

__device__ __forceinline__ void mma_bf16(float* d, const uint32_t* a, uint32_t b0, uint32_t b1) {
    asm volatile(
        "mma.sync.aligned.m16n8k16.row.col.f32.bf16.bf16.f32 "
        "{%0,%1,%2,%3}, {%4,%5,%6,%7}, {%8,%9}, {%0,%1,%2,%3};"
        : "+f"(d[0]), "+f"(d[1]), "+f"(d[2]), "+f"(d[3])
        : "r"(a[0]), "r"(a[1]), "r"(a[2]), "r"(a[3]), "r"(b0), "r"(b1));
}

// float4 -> two bf16x2 words
__device__ __forceinline__ uint2 pack4(float4 v) {
    __nv_bfloat162 a = __floats2bfloat162_rn(v.x, v.y);
    __nv_bfloat162 b = __floats2bfloat162_rn(v.z, v.w);
    return make_uint2(*(uint32_t*)&a, *(uint32_t*)&b);
}

// pack two f32 into e4m3x2 (result .b16; first PTX src packs the high byte)
__device__ __forceinline__ uint16_t f2e4m3x2(float a, float b) {
    uint16_t r;
    asm("cvt.rn.satfinite.e4m3x2.f32 %0, %1, %2;" : "=h"(r) : "f"(b), "f"(a));
    return r;
}

__global__ __launch_bounds__(256, 2)
void k_gemm_scatter(const float* __restrict__ A, const float* __restrict__ B, int M,
                    const int* __restrict__ esrc, const int* __restrict__ edst, int E) {
    __shared__ __nv_bfloat16 Ah[128 * AS];
    __shared__ __nv_bfloat16 Bh[16 * BSTR];

    int tid = threadIdx.x;
    int bm = blockIdx.x * 128;
    int bn = blockIdx.y * 128;
    int wid = tid >> 5;
    int lane = tid & 31;
    int wm = (wid & 3) * 32;
    int wn = (wid >> 2) * 64;
    int qr = lane >> 2, qc = lane & 3;

    int ar0 = (tid + 0) >> 2, ac0 = ((tid + 0) & 3) << 2;
    int ar1 = (tid + 256) >> 2, ac1 = ((tid + 256) & 3) << 2;
    int bk0 = (tid + 0) >> 5, bn0 = ((tid + 0) & 31) << 2;
    int bk1 = (tid + 256) >> 5, bn1 = ((tid + 256) & 31) << 2;

    int la = lane & 15, lb = lane >> 4;
    uint32_t adAh = smem_u32(Ah) + (uint32_t)(((wm + la) * AS + lb * 8) * 2);
    uint32_t adBh = smem_u32(Bh) + (uint32_t)((la * BSTR + wn + lb * 8) * 2);

    float d[2][8][4];
#pragma unroll
    for (int i = 0; i < 2; i++)
#pragma unroll
        for (int j = 0; j < 8; j++)
#pragma unroll
            for (int q = 0; q < 4; q++) d[i][j][q] = 0.0f;

    float4 pa0, pa1, pb0, pb1;
    {
        int g0 = bm + ar0, g1 = bm + ar1;
        pa0 = (g0 < M) ? *(const float4*)(A + (size_t)g0 * 256 + ac0) : make_float4(0.f, 0.f, 0.f, 0.f);
        pa1 = (g1 < M) ? *(const float4*)(A + (size_t)g1 * 256 + ac1) : make_float4(0.f, 0.f, 0.f, 0.f);
        pb0 = *(const float4*)(B + (size_t)bk0 * 256 + bn + bn0);
        pb1 = *(const float4*)(B + (size_t)bk1 * 256 + bn + bn1);
    }

    for (int t8 = 0; t8 < 16; t8++) {
        *(uint2*)&Ah[ar0 * AS + ac0] = pack4(pa0);
        *(uint2*)&Ah[ar1 * AS + ac1] = pack4(pa1);
        *(uint2*)&Bh[bk0 * BSTR + bn0] = pack4(pb0);
        *(uint2*)&Bh[bk1 * BSTR + bn1] = pack4(pb1);
        __syncthreads();

        if (t8 < 15) {
            int k0 = (t8 + 1) * 16;
            int g0 = bm + ar0, g1 = bm + ar1;
            pa0 = (g0 < M) ? *(const float4*)(A + (size_t)g0 * 256 + k0 + ac0) : make_float4(0.f, 0.f, 0.f, 0.f);
            pa1 = (g1 < M) ? *(const float4*)(A + (size_t)g1 * 256 + k0 + ac1) : make_float4(0.f, 0.f, 0.f, 0.f);
            pb0 = *(const float4*)(B + (size_t)(k0 + bk0) * 256 + bn + bn0);
            pb1 = *(const float4*)(B + (size_t)(k0 + bk1) * 256 + bn + bn1);
        }

        {
            uint32_t ah0[4], ah1[4];
            ldsm4(ah0, adAh);
            ldsm4(ah1, adAh + 16 * AS * 2);
#pragma unroll
            for (int t = 0; t < 4; t++) {
                uint32_t bh[4];
                ldsm4t(bh, adBh + t * 32);
                mma_bf16(d[0][2 * t],     ah0, bh[0], bh[1]);
                mma_bf16(d[1][2 * t],     ah1, bh[0], bh[1]);
                mma_bf16(d[0][2 * t + 1], ah0, bh[2], bh[3]);
                mma_bf16(d[1][2 * t + 1], ah1, bh[2], bh[3]);
            }
        }
        __syncthreads();
    }

    // epilogue: * dis[row], convert to e4m3 pairs, 2B stores
#pragma unroll
    for (int ma = 0; ma < 2; ma++) {
        int r0 = bm + wm + 16 * ma + qr;
        int r1 = r0 + 8;
        float w0 = (r0 < M) ? g_dis[r0] : 0.0f;
        float w1 = (r1 < M) ? g_dis[r1] : 0.0f;
#pragma unroll
        for (int na = 0; na < 8; na++) {
            int c = bn + wn + 8 * na + 2 * qc;
            if (r0 < M) {
                uint16_t p = f2e4m3x2(d[ma][na][0] * w0, d[ma][na][1] * w0);
                *(uint16_t*)(&g_h8[(size_t)r0 * 256 + c]) = p;
            }
            if (r1 < M) {
                uint16_t p = f2e4m3x2(d[ma][na][2] * w1, d[ma][na][3] * w1);
                *(uint16_t*)(&g_h8[(size_t)r1 * 256 + c]) = p;
            }
        }
    }

    // ---- tail: scatter this block's slice of edges into CSR (+ coef) ----
    {
        int nblocks = gridDim.x * gridDim.y;
        int bid = blockIdx.y * gridDim.x + blockIdx.x;
        int per = (E + nblocks - 1) / nblocks;
        int e0 = bid * per;
        int e1 = min(e0 + per, E);
        for (int i = e0 + tid; i < e1; i += 256) {
            int s = esrc[i];
            int dd = edst[i];
            int p = atomicAdd(&g_cursor[dd], 1);
            g_col[p] = s;
            atomicAdd(&g_coef[s], g_dis[dd]);
        }
    }
}

// -------------------- fused aggregation + weighted reduce -------------------
// 8 rows / block (one warp per row). Lane l owns cols l*8..l*8+7 = one uint2
// of 8 e4m3; unpack cvt.rn.f16x2.e4m3x2, accumulate half2. unroll 8 -> 8
// LDGs in flight vs ~250cyc L2 latency.

__device__ __forceinline__ __half2 e8_to_h2(uint16_t w) {
    uint32_t r;
    asm("cvt.rn.f16x2.e4m3x2 %0, %1;" : "=r"(r) : "h"(w));
    return *(__half2*)&r;
}

__global__ __launch_bounds__(256)
void k_agg_fused(const float* __restrict__ bias, int n) {
    __shared__ float sh[8][256];

    int lane = threadIdx.x & 31;
    int w = threadIdx.x >> 5;
    int i = blockIdx.x * 8 + w;

    const uint2* __restrict__ hp = (const uint2*)g_h8;  // row = 32 uint2
    float res[8];
#pragma unroll
    for (int q = 0; q < 8; q++) res[q] = 0.0f;

    if (i < n) {
        int s = g_rowptr[i];
        int t = g_rowptr[i + 1];
        float di = g_dis[i];
        float ci = di * (g_coef[i] + di);

        __half2 acc[4];
        {
            uint2 sv = hp[(size_t)i * 32 + lane];
            acc[0] = e8_to_h2((uint16_t)(sv.x & 0xffffu));
            acc[1] = e8_to_h2((uint16_t)(sv.x >> 16));
            acc[2] = e8_to_h2((uint16_t)(sv.y & 0xffffu));
            acc[3] = e8_to_h2((uint16_t)(sv.y >> 16));
        }

        for (int base = s; base < t; base += 32) {
            int m = min(32, t - base);
            int jv = (base + lane < t) ? g_col[base + lane] : 0;
#pragma unroll 8
            for (int k = 0; k < m; k++) {
                int j = __shfl_sync(0xffffffffu, jv, k);
                uint2 v = hp[(size_t)j * 32 + lane];
                acc[0] = __hadd2(acc[0], e8_to_h2((uint16_t)(v.x & 0xffffu)));
                acc[1] = __hadd2(acc[1], e8_to_h2((uint16_t)(v.x >> 16)));
                acc[2] = __hadd2(acc[2], e8_to_h2((uint16_t)(v.y & 0xffffu)));
                acc[3] = __hadd2(acc[3], e8_to_h2((uint16_t)(v.y >> 16)));
            }
        }

        float4 b0 = *(const float4*)(bias + lane * 8);
        float4 b1 = *(const float4*)(bias + lane * 8 + 4);
        float2 f0 = __half22float2(acc[0]);
        float2 f1 = __half22float2(acc[1]);
        float2 f2 = __half22float2(acc[2]);
        float2 f3 = __half22float2(acc[3]);
        res[0] = fmaxf(f0.x * di + b0.x, 0.f) * ci;
        res[1] = fmaxf(f0.y * di + b0.y, 0.f) * ci;
        res[2] = fmaxf(f1.x * di + b0.z, 0.f) * ci;
        res[3] = fmaxf(f1.y * di + b0.w, 0.f) * ci;
        res[4] = fmaxf(f2.x * di + b1.x, 0.f) * ci;
        res[5] = fmaxf(f2.y * di + b1.y, 0.f) * ci;
        res[6] = fmaxf(f3.x * di + b1.z, 0.f) * ci;
        res[7] = fmaxf(f3.y * di + b1.w, 0.f) * ci;
    }

#pragma unroll
    for (int q = 0; q < 8; q++) sh[w][lane * 8 + q] = res[q];
    __syncthreads();

    int c = threadIdx.x;
    float ssum = 0.0f;
#pragma unroll
    for (int q = 0; q < 8; q++) ssum += sh[q][c];
    g_part[(size_t)blockIdx.x * 256 + c] = ssum;
}

// ------------------------------- reductions --------------------------------

__global__ void k_reduce_stage1(int nb) {
    int c = threadIdx.x;
    int rows_per = (nb + 255) / 256;
    int r0 = blockIdx.x * rows_per;
    int r1 = min(r0 + rows_per, nb);
    float s = 0.0f;
    for (int r = r0; r < r1; r++) s += g_part[(size_t)r * 256 + c];
    g_part2[blockIdx.x * 256 + c] = s;
}

__global__ void k_final(const float* __restrict__ W2, const float* __restrict__ b2,
                        float* __restrict__ out, int n) {
    __shared__ float z[256];
    int c = threadIdx.x;
    float s = 0.0f;
    for (int b = 0; b < 256; b++) s += g_part2[b * 256 + c];
    z[c] = s / (float)n;
    __syncthreads();

    float o = b2[c];
#pragma unroll 8
    for (int k = 0; k < 256; k++) o += z[k] * W2[k * 256 + c];
    out[c] = o;
}

// -------------------------------- launch -----------------------------------

extern "C" void kernel_launch(void* const* d_in, const int* in_sizes, int n_in,
                              void* d_out, int out_size) {
    const float* x  = (const float*)d_in[0];
    const float* W1 = (const float*)d_in[1];
    const float* b1 = (const float*)d_in[2];
    const float* W2 = (const float*)d_in[3];
    const float* b2 = (const float*)d_in[4];
    const int*   ei = (const int*)d_in[5];

    int n = in_sizes[0] / DIM;
    int e = in_sizes[5] / 2;
    const int* src = ei;
    const int* dst = ei + e;
    float* out = (float*)d_out;

    int nb1024 = (n + 1023) / 1024;
    int agg_blocks = (n + 7) / 8;

    // zero deg/coef via memset nodes (not kernel launches)
    void* p_deg;
    void* p_coef;
    cudaGetSymbolAddress(&p_deg, g_deg);
    cudaGetSymbolAddress(&p_coef, g_coef);
    cudaMemsetAsync(p_deg, 0, (size_t)n * sizeof(int));
    cudaMemsetAsync(p_coef, 0, (size_t)n * sizeof(float));

    // --- degree / dis / rowptr ---
    k_count<<<(e + 255) / 256, 256>>>(dst, e);
    k_block_sums<<<nb1024, 256>>>(n);          // dis + block totals
    k_scan_blocks<<<nb1024, 1024>>>(n, e);     // rowptr + cursor

    // --- layer-1 GEMM (single-term bf16) with fused edge scatter tail ---
    dim3 gemm_grid((n + 127) / 128, 2);
    k_gemm_scatter<<<gemm_grid, 256>>>(x, W1, n, src, dst, e);

    // --- fused aggregate + relu + weighted reduce (layer 2 collapsed) ---
    k_agg_fused<<<agg_blocks, 256>>>(b1, n);

    // --- reduce partials, matvec with W2, bias, mean ---
    k_reduce_stage1<<<256, 256>>>(agg_blocks);
    k_final<<<1, 256>>>(W2, b2, out, n);
}